// round 1
// baseline (speedup 1.0000x reference)
#include <cuda_runtime.h>

#define EPS 1e-5f

// Intermediates (allocation-free scratch via __device__ globals)
static __device__ float g_buf1[256 * 16 * 4096];   // stage1 pooled output, 64 MB
static __device__ float g_buf2[256 * 32 * 1024];   // stage2 pooled output, 32 MB
static __device__ float g_part[256 * 32 * 64];     // stage3 per-(b,tile,psub) partial sums, 2 MB

__device__ __forceinline__ float ht(float x) { return fminf(1.f, fmaxf(-1.f, x)); }
__device__ __forceinline__ float sgn(float x) { return (x > 0.f) ? 1.f : ((x < 0.f) ? -1.f : 0.f); }

// ---------------------------------------------------------------------------
// Kernel 1: conv1 (1->16, K=17, s=2, p=8) + BN + hardtanh + maxpool2
// grid (16, 256), 128 threads. Each block: batch b, 256 pooled positions.
// Each thread: 2 pooled positions (= 4 conv outputs) for all 16 channels.
// ---------------------------------------------------------------------------
__global__ __launch_bounds__(128) void k1(
    const float* __restrict__ x, const float* __restrict__ w1,
    const float* __restrict__ g1, const float* __restrict__ b1,
    const float* __restrict__ m1, const float* __restrict__ v1)
{
    __shared__ float xs[1040];
    __shared__ float ws[16 * 17];
    __shared__ float sc[16], sh[16];

    const int b = blockIdx.y;
    const int p0 = blockIdx.x * 256;
    const int tid = threadIdx.x;

    for (int i = tid; i < 16 * 17; i += 128) ws[i] = w1[i];
    if (tid < 16) {
        float s = g1[tid] * rsqrtf(v1[tid] + EPS);
        sc[tid] = s;
        sh[tid] = b1[tid] - m1[tid] * s;
    }
    const float* xb = x + b * 16384;
    const int base = 4 * p0 - 8;
    for (int i = tid; i < 1039; i += 128) {
        int gi = base + i;
        xs[i] = (gi >= 0 && gi < 16384) ? xb[gi] : 0.f;
    }
    __syncthreads();

    float xin[23];
#pragma unroll
    for (int j = 0; j < 23; j++) xin[j] = xs[8 * tid + j];

    const int p = p0 + 2 * tid;
#pragma unroll 1
    for (int c = 0; c < 16; c++) {
        float a0 = 0.f, a1 = 0.f, a2 = 0.f, a3 = 0.f;
#pragma unroll
        for (int k = 0; k < 17; k++) {
            float w = ws[c * 17 + k];
            a0 = fmaf(w, xin[k], a0);
            a1 = fmaf(w, xin[k + 2], a1);
            a2 = fmaf(w, xin[k + 4], a2);
            a3 = fmaf(w, xin[k + 6], a3);
        }
        float s = sc[c], t = sh[c];
        a0 = ht(fmaf(a0, s, t));
        a1 = ht(fmaf(a1, s, t));
        a2 = ht(fmaf(a2, s, t));
        a3 = ht(fmaf(a3, s, t));
        float2 o;
        o.x = fmaxf(a0, a1);
        o.y = fmaxf(a2, a3);
        *(float2*)&g_buf1[(b * 16 + c) * 4096 + p] = o;
    }
}

// ---------------------------------------------------------------------------
// Kernel 2: conv2 (16->32, sign weights, K=9, s=2, p=4) + BN + ht + pool
// grid (64, 256), 128 threads. Block: batch b, 16 pooled positions.
// Thread (co = tid&31, pq = tid>>5): channel co, 4 pooled positions.
// ---------------------------------------------------------------------------
__global__ __launch_bounds__(128) void k2(
    const float* __restrict__ w2,
    const float* __restrict__ g2, const float* __restrict__ b2,
    const float* __restrict__ m2, const float* __restrict__ v2)
{
    __shared__ float ws[16 * 9 * 32];  // [ci][k][co]
    __shared__ float xs[16 * 72];      // [ci][71 cols]
    __shared__ float sc[32], sh[32];

    const int b = blockIdx.y;
    const int p0 = blockIdx.x * 16;
    const int tid = threadIdx.x;
    const int co = tid & 31;
    const int pq = tid >> 5;

    for (int i = tid; i < 4608; i += 128) {
        int c = i & 31;
        int r = i >> 5;
        int k = r % 9;
        int ci = r / 9;
        ws[i] = sgn(w2[c * 144 + ci * 9 + k]);
    }
    if (tid < 32) {
        float s = g2[tid] * rsqrtf(v2[tid] + EPS);
        sc[tid] = s;
        sh[tid] = b2[tid] - m2[tid] * s;
    }
    const float* in = g_buf1 + b * 16 * 4096;
    const int base = 4 * p0 - 4;
    for (int i = tid; i < 16 * 71; i += 128) {
        int row = i / 71, col = i % 71;
        int gi = base + col;
        xs[row * 72 + col] = (gi >= 0 && gi < 4096) ? in[row * 4096 + gi] : 0.f;
    }
    __syncthreads();

    float acc[8];
#pragma unroll
    for (int i = 0; i < 8; i++) acc[i] = 0.f;

#pragma unroll 1
    for (int ci = 0; ci < 16; ci++) {
        float xin[23];
#pragma unroll
        for (int j = 0; j < 23; j++) xin[j] = xs[ci * 72 + 16 * pq + j];
#pragma unroll
        for (int k = 0; k < 9; k++) {
            float w = ws[(ci * 9 + k) * 32 + co];
#pragma unroll
            for (int pp = 0; pp < 4; pp++) {
                acc[2 * pp]     = fmaf(w, xin[4 * pp + k], acc[2 * pp]);
                acc[2 * pp + 1] = fmaf(w, xin[4 * pp + 2 + k], acc[2 * pp + 1]);
            }
        }
    }
    float s = sc[co], t = sh[co];
    float4 o;
    o.x = fmaxf(ht(fmaf(acc[0], s, t)), ht(fmaf(acc[1], s, t)));
    o.y = fmaxf(ht(fmaf(acc[2], s, t)), ht(fmaf(acc[3], s, t)));
    o.z = fmaxf(ht(fmaf(acc[4], s, t)), ht(fmaf(acc[5], s, t)));
    o.w = fmaxf(ht(fmaf(acc[6], s, t)), ht(fmaf(acc[7], s, t)));
    *(float4*)&g_buf2[(b * 32 + co) * 1024 + p0 + 4 * pq] = o;
}

// ---------------------------------------------------------------------------
// Kernel 3: conv3 (32->64, sign weights, K=5, s=2, p=2) + BN + ht + pool
//           + partial mean accumulation.
// grid (8, 256), 256 threads, dynamic smem. Block: batch b, 32 pooled pos.
// Thread (co = tid&63, psub = tid>>6): channel co, 8 pooled positions.
// Writes one partial sum to g_part[((b*8+tile)*4+psub)*64+co].
// ---------------------------------------------------------------------------
__global__ __launch_bounds__(256) void k3(
    const float* __restrict__ w3,
    const float* __restrict__ g3, const float* __restrict__ b3,
    const float* __restrict__ m3, const float* __restrict__ v3)
{
    extern __shared__ float smem3[];
    float* ws = smem3;                 // [ci][k][co] = 32*5*64 = 10240
    float* xs = smem3 + 10240;         // [ci][132]   = 4224
    float* sc = xs + 32 * 132;         // [64]
    float* sh = sc + 64;               // [64]

    const int b = blockIdx.y;
    const int tile = blockIdx.x;
    const int p0 = tile * 32;
    const int tid = threadIdx.x;
    const int co = tid & 63;
    const int psub = tid >> 6;

    for (int i = tid; i < 10240; i += 256) {
        int c = i & 63;
        int r = i >> 6;
        int k = r % 5;
        int ci = r / 5;
        ws[i] = sgn(w3[c * 160 + ci * 5 + k]);
    }
    if (tid < 64) {
        float s = g3[tid] * rsqrtf(v3[tid] + EPS);
        sc[tid] = s;
        sh[tid] = b3[tid] - m3[tid] * s;
    }
    const float* in = g_buf2 + b * 32 * 1024;
    const int base = 4 * p0 - 2;
    for (int i = tid; i < 32 * 131; i += 256) {
        int row = i / 131, col = i % 131;
        int gi = base + col;
        xs[row * 132 + col] = (gi >= 0 && gi < 1024) ? in[row * 1024 + gi] : 0.f;
    }
    __syncthreads();

    float acc[16];
#pragma unroll
    for (int i = 0; i < 16; i++) acc[i] = 0.f;

#pragma unroll 1
    for (int ci = 0; ci < 32; ci++) {
        float xin[35];
#pragma unroll
        for (int j = 0; j < 35; j++) xin[j] = xs[ci * 132 + 32 * psub + j];
#pragma unroll
        for (int k = 0; k < 5; k++) {
            float w = ws[(ci * 5 + k) * 64 + co];
#pragma unroll
            for (int pp = 0; pp < 8; pp++) {
                acc[2 * pp]     = fmaf(w, xin[4 * pp + k], acc[2 * pp]);
                acc[2 * pp + 1] = fmaf(w, xin[4 * pp + 2 + k], acc[2 * pp + 1]);
            }
        }
    }
    float s = sc[co], t = sh[co];
    float sum = 0.f;
#pragma unroll
    for (int pp = 0; pp < 8; pp++)
        sum += fmaxf(ht(fmaf(acc[2 * pp], s, t)), ht(fmaf(acc[2 * pp + 1], s, t)));

    g_part[((b * 8 + tile) * 4 + psub) * 64 + co] = sum;
}

// ---------------------------------------------------------------------------
// Kernel 4: reduce partials -> mean, concat rms, fc1 + hardtanh, fc2.
// grid 256 (one block per batch), 64 threads.
// ---------------------------------------------------------------------------
__global__ __launch_bounds__(64) void k4(
    const float* __restrict__ rms,
    const float* __restrict__ fc1w, const float* __restrict__ fc1b,
    const float* __restrict__ fc2w, const float* __restrict__ fc2b,
    float* __restrict__ out)
{
    __shared__ float comb[65];
    __shared__ float h1[32];
    const int b = blockIdx.x;
    const int tid = threadIdx.x;

    {
        float s = 0.f;
        const float* base = g_part + b * 32 * 64 + tid;
#pragma unroll
        for (int j = 0; j < 32; j++) s += base[j * 64];
        comb[tid] = s * (1.f / 256.f);
    }
    if (tid == 0) comb[64] = rms[b];
    __syncthreads();

    if (tid < 32) {
        float a = fc1b[tid];
        const float* wr = fc1w + tid * 65;
#pragma unroll
        for (int i = 0; i < 65; i++) a = fmaf(comb[i], wr[i], a);
        h1[tid] = ht(a);
    }
    __syncthreads();

    if (tid < 2) {
        float a = fc2b[tid];
        const float* wr = fc2w + tid * 32;
#pragma unroll
        for (int i = 0; i < 32; i++) a = fmaf(h1[i], wr[i], a);
        out[b * 2 + tid] = a;
    }
}

// ---------------------------------------------------------------------------
extern "C" void kernel_launch(void* const* d_in, const int* in_sizes, int n_in,
                              void* d_out, int out_size)
{
    const float* x     = (const float*)d_in[0];
    const float* rms   = (const float*)d_in[1];
    const float* w1    = (const float*)d_in[2];
    const float* g1    = (const float*)d_in[3];
    const float* b1    = (const float*)d_in[4];
    const float* m1    = (const float*)d_in[5];
    const float* v1    = (const float*)d_in[6];
    const float* w2    = (const float*)d_in[7];
    const float* g2    = (const float*)d_in[8];
    const float* b2    = (const float*)d_in[9];
    const float* m2    = (const float*)d_in[10];
    const float* v2    = (const float*)d_in[11];
    const float* w3    = (const float*)d_in[12];
    const float* g3    = (const float*)d_in[13];
    const float* b3    = (const float*)d_in[14];
    const float* m3    = (const float*)d_in[15];
    const float* v3    = (const float*)d_in[16];
    const float* fc1w  = (const float*)d_in[17];
    const float* fc1b  = (const float*)d_in[18];
    const float* fc2w  = (const float*)d_in[19];
    const float* fc2b  = (const float*)d_in[20];
    float* out = (float*)d_out;

    const int k3_smem = (10240 + 32 * 132 + 128) * (int)sizeof(float);  // 58368 B
    cudaFuncSetAttribute(k3, cudaFuncAttributeMaxDynamicSharedMemorySize, k3_smem);

    k1<<<dim3(16, 256), 128>>>(x, w1, g1, b1, m1, v1);
    k2<<<dim3(64, 256), 128>>>(w2, g2, b2, m2, v2);
    k3<<<dim3(8, 256), 256, k3_smem>>>(w3, g3, b3, m3, v3);
    k4<<<256, 64>>>(rms, fc1w, fc1b, fc2w, fc2b, out);
}

// round 2
// speedup vs baseline: 1.2278x; 1.2278x over previous
#include <cuda_runtime.h>

#define EPS 1e-5f
typedef unsigned long long ull;

// Intermediates (allocation-free scratch via __device__ globals)
static __device__ float g_buf1[256 * 16 * 4096];   // stage1 pooled output
static __device__ float g_buf2[256 * 32 * 1024];   // stage2 pooled output
static __device__ float g_part[256 * 64 * 64];     // stage3 partial sums [b][group(64)][ch(64)]

__device__ __forceinline__ float ht(float x) { return fminf(1.f, fmaxf(-1.f, x)); }
__device__ __forceinline__ float sgn(float x) { return (x > 0.f) ? 1.f : ((x < 0.f) ? -1.f : 0.f); }

__device__ __forceinline__ ull fma2(ull a, ull b, ull c) {
    ull d; asm("fma.rn.f32x2 %0, %1, %2, %3;" : "=l"(d) : "l"(a), "l"(b), "l"(c)); return d;
}
__device__ __forceinline__ ull pk(float lo, float hi) {
    ull d; asm("mov.b64 %0, {%1, %2};" : "=l"(d) : "f"(lo), "f"(hi)); return d;
}
__device__ __forceinline__ void upk(ull d, float& lo, float& hi) {
    asm("mov.b64 {%0, %1}, %2;" : "=f"(lo), "=f"(hi) : "l"(d));
}

// ---------------------------------------------------------------------------
// Kernel 1: conv1 (1->16, K=17, s=2, p=8) + BN + hardtanh + maxpool2
// grid (16, 256), 128 threads. Channel-paired f32x2: 8 pairs of channels.
// Each thread: 2 pooled positions (4 conv outs) for all 8 channel-pairs.
// ---------------------------------------------------------------------------
__global__ __launch_bounds__(128) void k1(
    const float* __restrict__ x, const float* __restrict__ w1,
    const float* __restrict__ g1, const float* __restrict__ b1,
    const float* __restrict__ m1, const float* __restrict__ v1)
{
    __shared__ ull xs2[1040];        // (x,x) duplicated input tile
    __shared__ ull ws2[8 * 17];      // [pair][k] packed weights
    __shared__ ull sc2[8], sh2[8];

    const int b = blockIdx.y;
    const int p0 = blockIdx.x * 256;
    const int tid = threadIdx.x;

    for (int i = tid; i < 136; i += 128) {
        int pair = i / 17, k = i % 17;
        ws2[i] = pk(w1[(2 * pair) * 17 + k], w1[(2 * pair + 1) * 17 + k]);
    }
    if (tid < 8) {
        int c0 = 2 * tid, c1 = 2 * tid + 1;
        float s0 = g1[c0] * rsqrtf(v1[c0] + EPS);
        float s1 = g1[c1] * rsqrtf(v1[c1] + EPS);
        sc2[tid] = pk(s0, s1);
        sh2[tid] = pk(b1[c0] - m1[c0] * s0, b1[c1] - m1[c1] * s1);
    }
    const float* xb = x + b * 16384;
    const int base = 4 * p0 - 8;
    for (int i = tid; i < 1039; i += 128) {
        int gi = base + i;
        float v = (gi >= 0 && gi < 16384) ? xb[gi] : 0.f;
        xs2[i] = pk(v, v);
    }
    __syncthreads();

    ull xp[23];
#pragma unroll
    for (int j = 0; j < 23; j++) xp[j] = xs2[8 * tid + j];

    const int p = p0 + 2 * tid;
#pragma unroll 1
    for (int pair = 0; pair < 8; pair++) {
        ull a[4] = {0ull, 0ull, 0ull, 0ull};
#pragma unroll
        for (int k = 0; k < 17; k++) {
            ull w = ws2[pair * 17 + k];
#pragma unroll
            for (int j = 0; j < 4; j++) a[j] = fma2(w, xp[2 * j + k], a[j]);
        }
        ull s2 = sc2[pair], h2 = sh2[pair];
        float lo[4], hi[4];
#pragma unroll
        for (int j = 0; j < 4; j++) {
            a[j] = fma2(a[j], s2, h2);
            upk(a[j], lo[j], hi[j]);
        }
        float2 o0, o1;
        o0.x = fmaxf(ht(lo[0]), ht(lo[1])); o0.y = fmaxf(ht(lo[2]), ht(lo[3]));
        o1.x = fmaxf(ht(hi[0]), ht(hi[1])); o1.y = fmaxf(ht(hi[2]), ht(hi[3]));
        *(float2*)&g_buf1[(b * 16 + 2 * pair) * 4096 + p] = o0;
        *(float2*)&g_buf1[(b * 16 + 2 * pair + 1) * 4096 + p] = o1;
    }
}

// ---------------------------------------------------------------------------
// Kernel 2: conv2 (16->32, sign weights, K=9, s=2, p=4) + BN + ht + pool
// grid (32, 256), 128 threads. Thread (pair = tid&15, pq = tid>>4):
// channel-pair `pair`, 4 pooled positions (8 conv outputs), packed f32x2.
// ---------------------------------------------------------------------------
__global__ __launch_bounds__(128) void k2(
    const float* __restrict__ w2,
    const float* __restrict__ g2, const float* __restrict__ b2,
    const float* __restrict__ m2, const float* __restrict__ v2)
{
    __shared__ ull ws2[16 * 9 * 16];   // [(ci*9+k)*16 + pair]
    __shared__ ull xs2[16 * 136];      // [ci][135 cols] duplicated (x,x)
    __shared__ ull sc2[16], sh2[16];

    const int b = blockIdx.y;
    const int p0 = blockIdx.x * 32;    // 32 pooled positions per block
    const int tid = threadIdx.x;
    const int pair = tid & 15;
    const int pq = tid >> 4;

    for (int i = tid; i < 2304; i += 128) {
        int pr = i & 15, r = i >> 4;
        int k = r % 9, ci = r / 9;
        ws2[i] = pk(sgn(w2[(2 * pr) * 144 + ci * 9 + k]),
                    sgn(w2[(2 * pr + 1) * 144 + ci * 9 + k]));
    }
    if (tid < 16) {
        int c0 = 2 * tid, c1 = 2 * tid + 1;
        float s0 = g2[c0] * rsqrtf(v2[c0] + EPS);
        float s1 = g2[c1] * rsqrtf(v2[c1] + EPS);
        sc2[tid] = pk(s0, s1);
        sh2[tid] = pk(b2[c0] - m2[c0] * s0, b2[c1] - m2[c1] * s1);
    }
    const float* in = g_buf1 + b * 16 * 4096;
    const int base = 4 * p0 - 4;
    for (int i = tid; i < 16 * 135; i += 128) {
        int row = i / 135, col = i % 135;
        int gi = base + col;
        float v = (gi >= 0 && gi < 4096) ? in[row * 4096 + gi] : 0.f;
        xs2[row * 136 + col] = pk(v, v);
    }
    __syncthreads();

    ull acc[8];
#pragma unroll
    for (int j = 0; j < 8; j++) acc[j] = 0ull;

#pragma unroll 1
    for (int ci = 0; ci < 16; ci++) {
        ull xp[23];
#pragma unroll
        for (int j = 0; j < 23; j++) xp[j] = xs2[ci * 136 + 16 * pq + j];
#pragma unroll
        for (int k = 0; k < 9; k++) {
            ull w = ws2[(ci * 9 + k) * 16 + pair];
#pragma unroll
            for (int j = 0; j < 8; j++) acc[j] = fma2(w, xp[2 * j + k], acc[j]);
        }
    }

    ull s2 = sc2[pair], h2 = sh2[pair];
    float lo[8], hi[8];
#pragma unroll
    for (int j = 0; j < 8; j++) {
        acc[j] = fma2(acc[j], s2, h2);
        upk(acc[j], lo[j], hi[j]);
    }
    float4 o0, o1;
    o0.x = fmaxf(ht(lo[0]), ht(lo[1])); o0.y = fmaxf(ht(lo[2]), ht(lo[3]));
    o0.z = fmaxf(ht(lo[4]), ht(lo[5])); o0.w = fmaxf(ht(lo[6]), ht(lo[7]));
    o1.x = fmaxf(ht(hi[0]), ht(hi[1])); o1.y = fmaxf(ht(hi[2]), ht(hi[3]));
    o1.z = fmaxf(ht(hi[4]), ht(hi[5])); o1.w = fmaxf(ht(hi[6]), ht(hi[7]));
    const int pp = p0 + 4 * pq;
    *(float4*)&g_buf2[(b * 32 + 2 * pair) * 1024 + pp] = o0;
    *(float4*)&g_buf2[(b * 32 + 2 * pair + 1) * 1024 + pp] = o1;
}

// ---------------------------------------------------------------------------
// Kernel 3: conv3 (32->64, sign weights, K=5, s=2, p=2) + BN + ht + pool
//           + partial mean accumulation. Packed f32x2, channel-paired.
// grid (8, 256), 256 threads, dynamic smem. Thread (pair = tid&31, pq = tid>>5):
// channel-pair, 4 pooled positions. Partial sum -> g_part[b][tile*8+pq][ch].
// ---------------------------------------------------------------------------
__global__ __launch_bounds__(256) void k3(
    const float* __restrict__ w3,
    const float* __restrict__ g3, const float* __restrict__ b3,
    const float* __restrict__ m3, const float* __restrict__ v3)
{
    extern __shared__ ull smem3[];
    ull* ws2 = smem3;                  // 32*5*32 = 5120
    ull* xs2 = smem3 + 5120;           // 32*132  = 4224
    ull* sc2 = xs2 + 32 * 132;         // 32
    ull* sh2 = sc2 + 32;               // 32

    const int b = blockIdx.y;
    const int tile = blockIdx.x;
    const int p0 = tile * 32;
    const int tid = threadIdx.x;
    const int pair = tid & 31;
    const int pq = tid >> 5;

    for (int i = tid; i < 5120; i += 256) {
        int pr = i & 31, r = i >> 5;
        int k = r % 5, ci = r / 5;
        ws2[i] = pk(sgn(w3[(2 * pr) * 160 + ci * 5 + k]),
                    sgn(w3[(2 * pr + 1) * 160 + ci * 5 + k]));
    }
    if (tid < 32) {
        int c0 = 2 * tid, c1 = 2 * tid + 1;
        float s0 = g3[c0] * rsqrtf(v3[c0] + EPS);
        float s1 = g3[c1] * rsqrtf(v3[c1] + EPS);
        sc2[tid] = pk(s0, s1);
        sh2[tid] = pk(b3[c0] - m3[c0] * s0, b3[c1] - m3[c1] * s1);
    }
    const float* in = g_buf2 + b * 32 * 1024;
    const int base = 4 * p0 - 2;
    for (int i = tid; i < 32 * 131; i += 256) {
        int row = i / 131, col = i % 131;
        int gi = base + col;
        float v = (gi >= 0 && gi < 1024) ? in[row * 1024 + gi] : 0.f;
        xs2[row * 132 + col] = pk(v, v);
    }
    __syncthreads();

    ull acc[8];
#pragma unroll
    for (int j = 0; j < 8; j++) acc[j] = 0ull;

#pragma unroll 1
    for (int ci = 0; ci < 32; ci++) {
        ull xp[19];
#pragma unroll
        for (int j = 0; j < 19; j++) xp[j] = xs2[ci * 132 + 16 * pq + j];
#pragma unroll
        for (int k = 0; k < 5; k++) {
            ull w = ws2[(ci * 5 + k) * 32 + pair];
#pragma unroll
            for (int j = 0; j < 8; j++) acc[j] = fma2(w, xp[2 * j + k], acc[j]);
        }
    }

    ull s2 = sc2[pair], h2 = sh2[pair];
    float lo[8], hi[8];
#pragma unroll
    for (int j = 0; j < 8; j++) {
        acc[j] = fma2(acc[j], s2, h2);
        upk(acc[j], lo[j], hi[j]);
    }
    float sum0 = 0.f, sum1 = 0.f;
#pragma unroll
    for (int p = 0; p < 4; p++) {
        sum0 += fmaxf(ht(lo[2 * p]), ht(lo[2 * p + 1]));
        sum1 += fmaxf(ht(hi[2 * p]), ht(hi[2 * p + 1]));
    }
    const int grp = tile * 8 + pq;   // 0..63
    g_part[(b * 64 + grp) * 64 + 2 * pair] = sum0;
    g_part[(b * 64 + grp) * 64 + 2 * pair + 1] = sum1;
}

// ---------------------------------------------------------------------------
// Kernel 4: reduce partials -> mean, concat rms, fc1 + hardtanh, fc2.
// grid 256 (one block per batch), 64 threads.
// ---------------------------------------------------------------------------
__global__ __launch_bounds__(64) void k4(
    const float* __restrict__ rms,
    const float* __restrict__ fc1w, const float* __restrict__ fc1b,
    const float* __restrict__ fc2w, const float* __restrict__ fc2b,
    float* __restrict__ out)
{
    __shared__ float comb[65];
    __shared__ float h1[32];
    const int b = blockIdx.x;
    const int tid = threadIdx.x;

    {
        float s = 0.f;
        const float* base = g_part + b * 64 * 64 + tid;
#pragma unroll
        for (int j = 0; j < 64; j++) s += base[j * 64];
        comb[tid] = s * (1.f / 256.f);
    }
    if (tid == 0) comb[64] = rms[b];
    __syncthreads();

    if (tid < 32) {
        float a = fc1b[tid];
        const float* wr = fc1w + tid * 65;
#pragma unroll
        for (int i = 0; i < 65; i++) a = fmaf(comb[i], wr[i], a);
        h1[tid] = ht(a);
    }
    __syncthreads();

    if (tid < 2) {
        float a = fc2b[tid];
        const float* wr = fc2w + tid * 32;
#pragma unroll
        for (int i = 0; i < 32; i++) a = fmaf(h1[i], wr[i], a);
        out[b * 2 + tid] = a;
    }
}

// ---------------------------------------------------------------------------
extern "C" void kernel_launch(void* const* d_in, const int* in_sizes, int n_in,
                              void* d_out, int out_size)
{
    const float* x     = (const float*)d_in[0];
    const float* rms   = (const float*)d_in[1];
    const float* w1    = (const float*)d_in[2];
    const float* g1    = (const float*)d_in[3];
    const float* b1    = (const float*)d_in[4];
    const float* m1    = (const float*)d_in[5];
    const float* v1    = (const float*)d_in[6];
    const float* w2    = (const float*)d_in[7];
    const float* g2    = (const float*)d_in[8];
    const float* b2    = (const float*)d_in[9];
    const float* m2    = (const float*)d_in[10];
    const float* v2    = (const float*)d_in[11];
    const float* w3    = (const float*)d_in[12];
    const float* g3    = (const float*)d_in[13];
    const float* b3    = (const float*)d_in[14];
    const float* m3    = (const float*)d_in[15];
    const float* v3    = (const float*)d_in[16];
    const float* fc1w  = (const float*)d_in[17];
    const float* fc1b  = (const float*)d_in[18];
    const float* fc2w  = (const float*)d_in[19];
    const float* fc2b  = (const float*)d_in[20];
    float* out = (float*)d_out;

    const int k3_smem = (5120 + 32 * 132 + 64) * (int)sizeof(ull);  // ~75 KB
    cudaFuncSetAttribute(k3, cudaFuncAttributeMaxDynamicSharedMemorySize, k3_smem);

    k1<<<dim3(16, 256), 128>>>(x, w1, g1, b1, m1, v1);
    k2<<<dim3(32, 256), 128>>>(w2, g2, b2, m2, v2);
    k3<<<dim3(8, 256), 256, k3_smem>>>(w3, g3, b3, m3, v3);
    k4<<<256, 64>>>(rms, fc1w, fc1b, fc2w, fc2b, out);
}

// round 3
// speedup vs baseline: 1.5500x; 1.2624x over previous
#include <cuda_runtime.h>

#define EPS 1e-5f
typedef unsigned long long ull;
struct ull2 { ull x, y; };

// Intermediates (allocation-free scratch via __device__ globals)
static __device__ float g_buf1[256 * 16 * 4096];   // stage1 pooled output
static __device__ float g_buf2[256 * 32 * 1024];   // stage2 pooled output
static __device__ float g_part[256 * 64 * 64];     // stage3 partial sums

// Pre-packed weights (sign * BN-scale folded) + BN shifts, packed f32x2
static __device__ ull pw1[8 * 17];        // [pair][k]
static __device__ ull psh1[8];
static __device__ ull pw2[16 * 9 * 16];   // [(ci*9+k)*16 + pair]
static __device__ ull psh2[16];
static __device__ ull pw3[32 * 5 * 32];   // [(ci*5+k)*32 + pair]
static __device__ ull psh3[32];

__device__ __forceinline__ float ht(float x) { return fminf(1.f, fmaxf(-1.f, x)); }
__device__ __forceinline__ float sgn(float x) { return (x > 0.f) ? 1.f : ((x < 0.f) ? -1.f : 0.f); }

__device__ __forceinline__ ull fma2(ull a, ull b, ull c) {
    ull d; asm("fma.rn.f32x2 %0, %1, %2, %3;" : "=l"(d) : "l"(a), "l"(b), "l"(c)); return d;
}
__device__ __forceinline__ ull pk(float lo, float hi) {
    ull d; asm("mov.b64 %0, {%1, %2};" : "=l"(d) : "f"(lo), "f"(hi)); return d;
}
__device__ __forceinline__ void upk(ull d, float& lo, float& hi) {
    asm("mov.b64 {%0, %1}, %2;" : "=f"(lo), "=f"(hi) : "l"(d));
}

// ---------------------------------------------------------------------------
// k0a: pre-pack stage-1 and stage-2 weights (BN scale folded) + shifts
// ---------------------------------------------------------------------------
__global__ void k0a(
    const float* __restrict__ w1,
    const float* __restrict__ g1, const float* __restrict__ b1,
    const float* __restrict__ m1, const float* __restrict__ v1,
    const float* __restrict__ w2,
    const float* __restrict__ g2, const float* __restrict__ b2,
    const float* __restrict__ m2, const float* __restrict__ v2)
{
    const int tid = threadIdx.x;
    for (int i = tid; i < 136; i += 256) {
        int pair = i / 17, k = i % 17;
        int c0 = 2 * pair, c1 = c0 + 1;
        float s0 = g1[c0] * rsqrtf(v1[c0] + EPS);
        float s1 = g1[c1] * rsqrtf(v1[c1] + EPS);
        pw1[i] = pk(w1[c0 * 17 + k] * s0, w1[c1 * 17 + k] * s1);
    }
    if (tid < 8) {
        int c0 = 2 * tid, c1 = c0 + 1;
        float s0 = g1[c0] * rsqrtf(v1[c0] + EPS);
        float s1 = g1[c1] * rsqrtf(v1[c1] + EPS);
        psh1[tid] = pk(b1[c0] - m1[c0] * s0, b1[c1] - m1[c1] * s1);
    }
    for (int i = tid; i < 2304; i += 256) {
        int pr = i & 15, r = i >> 4;
        int k = r % 9, ci = r / 9;
        int c0 = 2 * pr, c1 = c0 + 1;
        float s0 = g2[c0] * rsqrtf(v2[c0] + EPS);
        float s1 = g2[c1] * rsqrtf(v2[c1] + EPS);
        pw2[i] = pk(sgn(w2[c0 * 144 + ci * 9 + k]) * s0,
                    sgn(w2[c1 * 144 + ci * 9 + k]) * s1);
    }
    if (tid < 16) {
        int c0 = 2 * tid, c1 = c0 + 1;
        float s0 = g2[c0] * rsqrtf(v2[c0] + EPS);
        float s1 = g2[c1] * rsqrtf(v2[c1] + EPS);
        psh2[tid] = pk(b2[c0] - m2[c0] * s0, b2[c1] - m2[c1] * s1);
    }
}

// ---------------------------------------------------------------------------
// k0b: pre-pack stage-3 weights + shifts
// ---------------------------------------------------------------------------
__global__ void k0b(
    const float* __restrict__ w3,
    const float* __restrict__ g3, const float* __restrict__ b3,
    const float* __restrict__ m3, const float* __restrict__ v3)
{
    const int tid = threadIdx.x;
    for (int i = tid; i < 5120; i += 256) {
        int pr = i & 31, r = i >> 5;
        int k = r % 5, ci = r / 5;
        int c0 = 2 * pr, c1 = c0 + 1;
        float s0 = g3[c0] * rsqrtf(v3[c0] + EPS);
        float s1 = g3[c1] * rsqrtf(v3[c1] + EPS);
        pw3[i] = pk(sgn(w3[c0 * 160 + ci * 5 + k]) * s0,
                    sgn(w3[c1 * 160 + ci * 5 + k]) * s1);
    }
    if (tid < 32) {
        int c0 = 2 * tid, c1 = c0 + 1;
        float s0 = g3[c0] * rsqrtf(v3[c0] + EPS);
        float s1 = g3[c1] * rsqrtf(v3[c1] + EPS);
        psh3[tid] = pk(b3[c0] - m3[c0] * s0, b3[c1] - m3[c1] * s1);
    }
}

// ---------------------------------------------------------------------------
// Kernel 1: conv1 (1->16, K=17, s=2, p=8) + BN + hardtanh + maxpool2
// ---------------------------------------------------------------------------
__global__ __launch_bounds__(128) void k1(const float* __restrict__ x)
{
    __shared__ ull xs2[1040];
    __shared__ ull ws2[8 * 17];
    __shared__ ull sh2[8];

    const int b = blockIdx.y;
    const int p0 = blockIdx.x * 256;
    const int tid = threadIdx.x;

    for (int i = tid; i < 136; i += 128) ws2[i] = pw1[i];
    if (tid < 8) sh2[tid] = psh1[tid];

    const float* xb = x + b * 16384;
    const int base = 4 * p0 - 8;
    for (int i = tid; i < 1039; i += 128) {
        int gi = base + i;
        float v = (gi >= 0 && gi < 16384) ? xb[gi] : 0.f;
        xs2[i] = pk(v, v);
    }
    __syncthreads();

    ull xp[23];
#pragma unroll
    for (int j = 0; j < 11; j++) {
        ull2 t = *(const ull2*)&xs2[8 * tid + 2 * j];
        xp[2 * j] = t.x; xp[2 * j + 1] = t.y;
    }
    xp[22] = xs2[8 * tid + 22];

    const int p = p0 + 2 * tid;
#pragma unroll 1
    for (int pair = 0; pair < 8; pair++) {
        ull h2 = sh2[pair];
        ull a[4] = {h2, h2, h2, h2};
#pragma unroll
        for (int k = 0; k < 17; k++) {
            ull w = ws2[pair * 17 + k];
#pragma unroll
            for (int j = 0; j < 4; j++) a[j] = fma2(w, xp[2 * j + k], a[j]);
        }
        float lo[4], hi[4];
#pragma unroll
        for (int j = 0; j < 4; j++) upk(a[j], lo[j], hi[j]);
        float2 o0, o1;
        o0.x = fmaxf(ht(lo[0]), ht(lo[1])); o0.y = fmaxf(ht(lo[2]), ht(lo[3]));
        o1.x = fmaxf(ht(hi[0]), ht(hi[1])); o1.y = fmaxf(ht(hi[2]), ht(hi[3]));
        *(float2*)&g_buf1[(b * 16 + 2 * pair) * 4096 + p] = o0;
        *(float2*)&g_buf1[(b * 16 + 2 * pair + 1) * 4096 + p] = o1;
    }
}

// ---------------------------------------------------------------------------
// Kernel 2: conv2 (16->32, sign weights*s, K=9, s=2, p=4) + ht + pool
// ---------------------------------------------------------------------------
__global__ __launch_bounds__(128) void k2()
{
    __shared__ ull ws2[16 * 9 * 16];
    __shared__ ull xs2[16 * 136];
    __shared__ ull sh2[16];

    const int b = blockIdx.y;
    const int p0 = blockIdx.x * 32;
    const int tid = threadIdx.x;
    const int pair = tid & 15;
    const int pq = tid >> 4;

    for (int i = tid; i < 2304; i += 128) ws2[i] = pw2[i];
    if (tid < 16) sh2[tid] = psh2[tid];

    const float* in = g_buf1 + b * 16 * 4096;
    const int base = 4 * p0 - 4;
    for (int i = tid; i < 16 * 135; i += 128) {
        int row = i / 135, col = i % 135;
        int gi = base + col;
        float v = (gi >= 0 && gi < 4096) ? in[row * 4096 + gi] : 0.f;
        xs2[row * 136 + col] = pk(v, v);
    }
    __syncthreads();

    ull h2 = sh2[pair];
    ull acc[8];
#pragma unroll
    for (int j = 0; j < 8; j++) acc[j] = h2;

#pragma unroll 1
    for (int ci = 0; ci < 16; ci++) {
        ull xp[23];
#pragma unroll
        for (int j = 0; j < 11; j++) {
            ull2 t = *(const ull2*)&xs2[ci * 136 + 16 * pq + 2 * j];
            xp[2 * j] = t.x; xp[2 * j + 1] = t.y;
        }
        xp[22] = xs2[ci * 136 + 16 * pq + 22];
#pragma unroll
        for (int k = 0; k < 9; k++) {
            ull w = ws2[(ci * 9 + k) * 16 + pair];
#pragma unroll
            for (int j = 0; j < 8; j++) acc[j] = fma2(w, xp[2 * j + k], acc[j]);
        }
    }

    float lo[8], hi[8];
#pragma unroll
    for (int j = 0; j < 8; j++) upk(acc[j], lo[j], hi[j]);
    float4 o0, o1;
    o0.x = fmaxf(ht(lo[0]), ht(lo[1])); o0.y = fmaxf(ht(lo[2]), ht(lo[3]));
    o0.z = fmaxf(ht(lo[4]), ht(lo[5])); o0.w = fmaxf(ht(lo[6]), ht(lo[7]));
    o1.x = fmaxf(ht(hi[0]), ht(hi[1])); o1.y = fmaxf(ht(hi[2]), ht(hi[3]));
    o1.z = fmaxf(ht(hi[4]), ht(hi[5])); o1.w = fmaxf(ht(hi[6]), ht(hi[7]));
    const int pp = p0 + 4 * pq;
    *(float4*)&g_buf2[(b * 32 + 2 * pair) * 1024 + pp] = o0;
    *(float4*)&g_buf2[(b * 32 + 2 * pair + 1) * 1024 + pp] = o1;
}

// ---------------------------------------------------------------------------
// Kernel 3: conv3 (32->64, sign weights*s, K=5, s=2, p=2) + ht + pool + partials
// ---------------------------------------------------------------------------
__global__ __launch_bounds__(256) void k3()
{
    extern __shared__ ull smem3[];
    ull* ws2 = smem3;                  // 5120
    ull* xs2 = smem3 + 5120;           // 32*132
    ull* sh2 = xs2 + 32 * 132;         // 32

    const int b = blockIdx.y;
    const int tile = blockIdx.x;
    const int p0 = tile * 32;
    const int tid = threadIdx.x;
    const int pair = tid & 31;
    const int pq = tid >> 5;

    for (int i = tid; i < 5120; i += 256) ws2[i] = pw3[i];
    if (tid < 32) sh2[tid] = psh3[tid];

    const float* in = g_buf2 + b * 32 * 1024;
    const int base = 4 * p0 - 2;
    for (int i = tid; i < 32 * 131; i += 256) {
        int row = i / 131, col = i % 131;
        int gi = base + col;
        float v = (gi >= 0 && gi < 1024) ? in[row * 1024 + gi] : 0.f;
        xs2[row * 132 + col] = pk(v, v);
    }
    __syncthreads();

    ull h2 = sh2[pair];
    ull acc[8];
#pragma unroll
    for (int j = 0; j < 8; j++) acc[j] = h2;

#pragma unroll 1
    for (int ci = 0; ci < 32; ci++) {
        ull xp[19];
#pragma unroll
        for (int j = 0; j < 9; j++) {
            ull2 t = *(const ull2*)&xs2[ci * 132 + 16 * pq + 2 * j];
            xp[2 * j] = t.x; xp[2 * j + 1] = t.y;
        }
        xp[18] = xs2[ci * 132 + 16 * pq + 18];
#pragma unroll
        for (int k = 0; k < 5; k++) {
            ull w = ws2[(ci * 5 + k) * 32 + pair];
#pragma unroll
            for (int j = 0; j < 8; j++) acc[j] = fma2(w, xp[2 * j + k], acc[j]);
        }
    }

    float lo[8], hi[8];
#pragma unroll
    for (int j = 0; j < 8; j++) upk(acc[j], lo[j], hi[j]);
    float sum0 = 0.f, sum1 = 0.f;
#pragma unroll
    for (int p = 0; p < 4; p++) {
        sum0 += fmaxf(ht(lo[2 * p]), ht(lo[2 * p + 1]));
        sum1 += fmaxf(ht(hi[2 * p]), ht(hi[2 * p + 1]));
    }
    const int grp = tile * 8 + pq;
    g_part[(b * 64 + grp) * 64 + 2 * pair] = sum0;
    g_part[(b * 64 + grp) * 64 + 2 * pair + 1] = sum1;
}

// ---------------------------------------------------------------------------
// Kernel 4: reduce partials -> mean, concat rms, fc1 + hardtanh, fc2
// ---------------------------------------------------------------------------
__global__ __launch_bounds__(64) void k4(
    const float* __restrict__ rms,
    const float* __restrict__ fc1w, const float* __restrict__ fc1b,
    const float* __restrict__ fc2w, const float* __restrict__ fc2b,
    float* __restrict__ out)
{
    __shared__ float comb[65];
    __shared__ float h1[32];
    const int b = blockIdx.x;
    const int tid = threadIdx.x;

    {
        float s = 0.f;
        const float* base = g_part + b * 64 * 64 + tid;
#pragma unroll
        for (int j = 0; j < 64; j++) s += base[j * 64];
        comb[tid] = s * (1.f / 256.f);
    }
    if (tid == 0) comb[64] = rms[b];
    __syncthreads();

    if (tid < 32) {
        float a = fc1b[tid];
        const float* wr = fc1w + tid * 65;
#pragma unroll
        for (int i = 0; i < 65; i++) a = fmaf(comb[i], wr[i], a);
        h1[tid] = ht(a);
    }
    __syncthreads();

    if (tid < 2) {
        float a = fc2b[tid];
        const float* wr = fc2w + tid * 32;
#pragma unroll
        for (int i = 0; i < 32; i++) a = fmaf(h1[i], wr[i], a);
        out[b * 2 + tid] = a;
    }
}

// ---------------------------------------------------------------------------
extern "C" void kernel_launch(void* const* d_in, const int* in_sizes, int n_in,
                              void* d_out, int out_size)
{
    const float* x     = (const float*)d_in[0];
    const float* rms   = (const float*)d_in[1];
    const float* w1    = (const float*)d_in[2];
    const float* g1    = (const float*)d_in[3];
    const float* b1    = (const float*)d_in[4];
    const float* m1    = (const float*)d_in[5];
    const float* v1    = (const float*)d_in[6];
    const float* w2    = (const float*)d_in[7];
    const float* g2    = (const float*)d_in[8];
    const float* b2    = (const float*)d_in[9];
    const float* m2    = (const float*)d_in[10];
    const float* v2    = (const float*)d_in[11];
    const float* w3    = (const float*)d_in[12];
    const float* g3    = (const float*)d_in[13];
    const float* b3    = (const float*)d_in[14];
    const float* m3    = (const float*)d_in[15];
    const float* v3    = (const float*)d_in[16];
    const float* fc1w  = (const float*)d_in[17];
    const float* fc1b  = (const float*)d_in[18];
    const float* fc2w  = (const float*)d_in[19];
    const float* fc2b  = (const float*)d_in[20];
    float* out = (float*)d_out;

    const int k3_smem = (5120 + 32 * 132 + 32) * (int)sizeof(ull);
    cudaFuncSetAttribute(k3, cudaFuncAttributeMaxDynamicSharedMemorySize, k3_smem);

    k0a<<<1, 256>>>(w1, g1, b1, m1, v1, w2, g2, b2, m2, v2);
    k0b<<<1, 256>>>(w3, g3, b3, m3, v3);
    k1<<<dim3(16, 256), 128>>>(x);
    k2<<<dim3(32, 256), 128>>>();
    k3<<<dim3(8, 256), 256, k3_smem>>>();
    k4<<<256, 64>>>(rms, fc1w, fc1b, fc2w, fc2b, out);
}

// round 4
// speedup vs baseline: 1.6365x; 1.0558x over previous
#include <cuda_runtime.h>

#define EPS 1e-5f
typedef unsigned long long ull;
struct ull2x { ull x, y; };

// Batch-pair interleaved intermediates: lane0=batch 2bp, lane1=batch 2bp+1
static __device__ ull g_buf1u[128 * 16 * 4096];  // stage1 pooled [bp][ch][pos]
static __device__ ull g_buf2u[128 * 32 * 1024];  // stage2 pooled [bp][ch][pos]
static __device__ ull g_partu[128 * 128 * 64];   // stage3 partials [bp][group][ch]

// Pre-packed weights: value duplicated in both lanes (lanes are batches)
static __device__ ull pw1[16 * 17];       // [ch][k]   (w*s, w*s)
static __device__ ull psh1[16];
static __device__ ull pw2[16 * 9 * 32];   // [(ci*9+k)*32 + co]
static __device__ ull psh2[32];
static __device__ ull pw3[32 * 5 * 64];   // [(ci*5+k)*64 + co]
static __device__ ull psh3[64];

__device__ __forceinline__ float ht(float x) { return fminf(1.f, fmaxf(-1.f, x)); }
__device__ __forceinline__ float sgn(float x) { return (x > 0.f) ? 1.f : ((x < 0.f) ? -1.f : 0.f); }

__device__ __forceinline__ ull fma2(ull a, ull b, ull c) {
    ull d; asm("fma.rn.f32x2 %0, %1, %2, %3;" : "=l"(d) : "l"(a), "l"(b), "l"(c)); return d;
}
__device__ __forceinline__ ull add2(ull a, ull b) {
    ull d; asm("add.rn.f32x2 %0, %1, %2;" : "=l"(d) : "l"(a), "l"(b)); return d;
}
__device__ __forceinline__ ull pk(float lo, float hi) {
    ull d; asm("mov.b64 %0, {%1, %2};" : "=l"(d) : "f"(lo), "f"(hi)); return d;
}
__device__ __forceinline__ void upk(ull d, float& lo, float& hi) {
    asm("mov.b64 {%0, %1}, %2;" : "=f"(lo), "=f"(hi) : "l"(d));
}

// ---------------------------------------------------------------------------
// k0a: pre-pack stage-1/2 weights (BN scale folded, duplicated lanes) + shifts
// ---------------------------------------------------------------------------
__global__ void k0a(
    const float* __restrict__ w1,
    const float* __restrict__ g1, const float* __restrict__ b1,
    const float* __restrict__ m1, const float* __restrict__ v1,
    const float* __restrict__ w2,
    const float* __restrict__ g2, const float* __restrict__ b2,
    const float* __restrict__ m2, const float* __restrict__ v2)
{
    const int tid = threadIdx.x;
    for (int i = tid; i < 272; i += 256) {
        int ch = i / 17, k = i % 17;
        float s = g1[ch] * rsqrtf(v1[ch] + EPS);
        float v = w1[ch * 17 + k] * s;
        pw1[i] = pk(v, v);
    }
    if (tid < 16) {
        float s = g1[tid] * rsqrtf(v1[tid] + EPS);
        float t = b1[tid] - m1[tid] * s;
        psh1[tid] = pk(t, t);
    }
    for (int i = tid; i < 4608; i += 256) {
        int co = i & 31, r = i >> 5;
        int k = r % 9, ci = r / 9;
        float s = g2[co] * rsqrtf(v2[co] + EPS);
        float v = sgn(w2[co * 144 + ci * 9 + k]) * s;
        pw2[i] = pk(v, v);
    }
    if (tid < 32) {
        float s = g2[tid] * rsqrtf(v2[tid] + EPS);
        float t = b2[tid] - m2[tid] * s;
        psh2[tid] = pk(t, t);
    }
}

// ---------------------------------------------------------------------------
// k0b: pre-pack stage-3 weights + shifts
// ---------------------------------------------------------------------------
__global__ void k0b(
    const float* __restrict__ w3,
    const float* __restrict__ g3, const float* __restrict__ b3,
    const float* __restrict__ m3, const float* __restrict__ v3)
{
    const int tid = threadIdx.x;
    for (int i = tid; i < 10240; i += 256) {
        int co = i & 63, r = i >> 6;
        int k = r % 5, ci = r / 5;
        float s = g3[co] * rsqrtf(v3[co] + EPS);
        float v = sgn(w3[co * 160 + ci * 5 + k]) * s;
        pw3[i] = pk(v, v);
    }
    if (tid < 64) {
        float s = g3[tid] * rsqrtf(v3[tid] + EPS);
        float t = b3[tid] - m3[tid] * s;
        psh3[tid] = pk(t, t);
    }
}

// ---------------------------------------------------------------------------
// Kernel 1: conv1 (1->16, K=17, s=2, p=8) + BN + ht + pool. Batch-pair lanes.
// grid (16, 128), 128 thr. Thread: 2 pooled positions x 16 channels.
// ---------------------------------------------------------------------------
__global__ __launch_bounds__(128) void k1(const float* __restrict__ x)
{
    __shared__ ull xs[1040];
    __shared__ ull ws[272];
    __shared__ ull sh[16];

    const int bp = blockIdx.y;
    const int p0 = blockIdx.x * 256;
    const int tid = threadIdx.x;

    for (int i = tid; i < 272; i += 128) ws[i] = pw1[i];
    if (tid < 16) sh[tid] = psh1[tid];

    const float* xb0 = x + (2 * bp) * 16384;
    const float* xb1 = xb0 + 16384;
    const int base = 4 * p0 - 8;
    for (int i = tid; i < 1039; i += 128) {
        int gi = base + i;
        xs[i] = (gi >= 0 && gi < 16384) ? pk(xb0[gi], xb1[gi]) : 0ull;
    }
    __syncthreads();

    ull xp[23];
#pragma unroll
    for (int j = 0; j < 11; j++) {
        ull2x t = *(const ull2x*)&xs[8 * tid + 2 * j];
        xp[2 * j] = t.x; xp[2 * j + 1] = t.y;
    }
    xp[22] = xs[8 * tid + 22];

    const int p = p0 + 2 * tid;
#pragma unroll 1
    for (int ch = 0; ch < 16; ch++) {
        ull h2 = sh[ch];
        ull a[4] = {h2, h2, h2, h2};
#pragma unroll
        for (int k = 0; k < 17; k++) {
            ull w = ws[ch * 17 + k];
#pragma unroll
            for (int j = 0; j < 4; j++) a[j] = fma2(w, xp[2 * j + k], a[j]);
        }
        float lo[4], hi[4];
#pragma unroll
        for (int j = 0; j < 4; j++) upk(a[j], lo[j], hi[j]);
        ull2x o;
        o.x = pk(ht(fmaxf(lo[0], lo[1])), ht(fmaxf(hi[0], hi[1])));
        o.y = pk(ht(fmaxf(lo[2], lo[3])), ht(fmaxf(hi[2], hi[3])));
        *(ull2x*)&g_buf1u[(bp * 16 + ch) * 4096 + p] = o;
    }
}

// ---------------------------------------------------------------------------
// Kernel 2: conv2 (16->32, +-s weights, K=9, s=2, p=4) + ht + pool.
// grid (64, 128), 256 thr. Thread (co=tid&31, pq=tid>>5): 1 channel x 2 pooled
// x 2 batches. Weights from global (L1-resident).
// ---------------------------------------------------------------------------
__global__ __launch_bounds__(256, 4) void k2()
{
    __shared__ ull xs2[16 * 72];

    const int bp = blockIdx.y;
    const int p0 = blockIdx.x * 16;
    const int tid = threadIdx.x;
    const int co = tid & 31;
    const int pq = tid >> 5;   // 0..7

    const ull* __restrict__ in = g_buf1u + bp * 16 * 4096;
    const int base = 4 * p0 - 4;
    for (int i = tid; i < 16 * 71; i += 256) {
        int row = i / 71, col = i % 71;
        int gi = base + col;
        xs2[row * 72 + col] = (gi >= 0 && gi < 4096) ? in[row * 4096 + gi] : 0ull;
    }
    __syncthreads();

    ull h2 = psh2[co];
    ull acc[4] = {h2, h2, h2, h2};
    const ull* __restrict__ wp = pw2 + co;

#pragma unroll 1
    for (int ci = 0; ci < 16; ci++) {
        ull xp[15];
#pragma unroll
        for (int j = 0; j < 7; j++) {
            ull2x t = *(const ull2x*)&xs2[ci * 72 + 8 * pq + 2 * j];
            xp[2 * j] = t.x; xp[2 * j + 1] = t.y;
        }
        xp[14] = xs2[ci * 72 + 8 * pq + 14];
#pragma unroll
        for (int k = 0; k < 9; k++) {
            ull w = wp[(ci * 9 + k) * 32];
#pragma unroll
            for (int j = 0; j < 4; j++) acc[j] = fma2(w, xp[2 * j + k], acc[j]);
        }
    }

    float lo[4], hi[4];
#pragma unroll
    for (int j = 0; j < 4; j++) upk(acc[j], lo[j], hi[j]);
    ull2x o;
    o.x = pk(ht(fmaxf(lo[0], lo[1])), ht(fmaxf(hi[0], hi[1])));
    o.y = pk(ht(fmaxf(lo[2], lo[3])), ht(fmaxf(hi[2], hi[3])));
    *(ull2x*)&g_buf2u[(bp * 32 + co) * 1024 + p0 + 2 * pq] = o;
}

// ---------------------------------------------------------------------------
// Kernel 3: conv3 (32->64, +-s weights, K=5, s=2, p=2) + ht + pool + partials.
// grid (32, 128), 256 thr. Thread (co=tid&63, pq=tid>>6): 1 channel x 2 pooled
// x 2 batches. Weights from global (L1-resident).
// ---------------------------------------------------------------------------
__global__ __launch_bounds__(256, 4) void k3()
{
    __shared__ ull xs3[32 * 36];

    const int bp = blockIdx.y;
    const int p0 = blockIdx.x * 8;
    const int tid = threadIdx.x;
    const int co = tid & 63;
    const int pq = tid >> 6;   // 0..3

    const ull* __restrict__ in = g_buf2u + bp * 32 * 1024;
    const int base = 4 * p0 - 2;
    for (int i = tid; i < 32 * 35; i += 256) {
        int row = i / 35, col = i % 35;
        int gi = base + col;
        xs3[row * 36 + col] = (gi >= 0 && gi < 1024) ? in[row * 1024 + gi] : 0ull;
    }
    __syncthreads();

    ull h2 = psh3[co];
    ull acc[4] = {h2, h2, h2, h2};
    const ull* __restrict__ wp = pw3 + co;

#pragma unroll 1
    for (int ci = 0; ci < 32; ci++) {
        ull xp[11];
#pragma unroll
        for (int j = 0; j < 5; j++) {
            ull2x t = *(const ull2x*)&xs3[ci * 36 + 8 * pq + 2 * j];
            xp[2 * j] = t.x; xp[2 * j + 1] = t.y;
        }
        xp[10] = xs3[ci * 36 + 8 * pq + 10];
#pragma unroll
        for (int k = 0; k < 5; k++) {
            ull w = wp[(ci * 5 + k) * 64];
#pragma unroll
            for (int j = 0; j < 4; j++) acc[j] = fma2(w, xp[2 * j + k], acc[j]);
        }
    }

    float lo[4], hi[4];
#pragma unroll
    for (int j = 0; j < 4; j++) upk(acc[j], lo[j], hi[j]);
    float s0 = ht(fmaxf(lo[0], lo[1])) + ht(fmaxf(lo[2], lo[3]));
    float s1 = ht(fmaxf(hi[0], hi[1])) + ht(fmaxf(hi[2], hi[3]));
    const int grp = blockIdx.x * 4 + pq;   // 0..127
    g_partu[(bp * 128 + grp) * 64 + co] = pk(s0, s1);
}

// ---------------------------------------------------------------------------
// Kernel 4: reduce partials -> mean, concat rms, fc1 + ht, fc2. Per batch-pair.
// grid 128, 128 thr.
// ---------------------------------------------------------------------------
__global__ __launch_bounds__(128) void k4(
    const float* __restrict__ rms,
    const float* __restrict__ fc1w, const float* __restrict__ fc1b,
    const float* __restrict__ fc2w, const float* __restrict__ fc2b,
    float* __restrict__ out)
{
    __shared__ float comb[2][65];
    __shared__ float h1[2][32];
    const int bp = blockIdx.x;
    const int tid = threadIdx.x;

    if (tid < 64) {
        ull s = 0ull;
        const ull* basep = g_partu + bp * 128 * 64 + tid;
#pragma unroll
        for (int g = 0; g < 128; g++) s = add2(s, basep[g * 64]);
        float a, b; upk(s, a, b);
        comb[0][tid] = a * (1.f / 256.f);
        comb[1][tid] = b * (1.f / 256.f);
    }
    if (tid == 64) { comb[0][64] = rms[2 * bp]; }
    if (tid == 65) { comb[1][64] = rms[2 * bp + 1]; }
    __syncthreads();

    const int half = tid >> 6;
    const int t = tid & 63;
    if (t < 32) {
        float a = fc1b[t];
        const float* wr = fc1w + t * 65;
        const float* cb = comb[half];
#pragma unroll
        for (int i = 0; i < 65; i++) a = fmaf(cb[i], wr[i], a);
        h1[half][t] = ht(a);
    }
    __syncthreads();

    if (t < 2) {
        float a = fc2b[t];
        const float* wr = fc2w + t * 32;
        const float* hh = h1[half];
#pragma unroll
        for (int i = 0; i < 32; i++) a = fmaf(hh[i], wr[i], a);
        out[(2 * bp + half) * 2 + t] = a;
    }
}

// ---------------------------------------------------------------------------
extern "C" void kernel_launch(void* const* d_in, const int* in_sizes, int n_in,
                              void* d_out, int out_size)
{
    const float* x     = (const float*)d_in[0];
    const float* rms   = (const float*)d_in[1];
    const float* w1    = (const float*)d_in[2];
    const float* g1    = (const float*)d_in[3];
    const float* b1    = (const float*)d_in[4];
    const float* m1    = (const float*)d_in[5];
    const float* v1    = (const float*)d_in[6];
    const float* w2    = (const float*)d_in[7];
    const float* g2    = (const float*)d_in[8];
    const float* b2    = (const float*)d_in[9];
    const float* m2    = (const float*)d_in[10];
    const float* v2    = (const float*)d_in[11];
    const float* w3    = (const float*)d_in[12];
    const float* g3    = (const float*)d_in[13];
    const float* b3    = (const float*)d_in[14];
    const float* m3    = (const float*)d_in[15];
    const float* v3    = (const float*)d_in[16];
    const float* fc1w  = (const float*)d_in[17];
    const float* fc1b  = (const float*)d_in[18];
    const float* fc2w  = (const float*)d_in[19];
    const float* fc2b  = (const float*)d_in[20];
    float* out = (float*)d_out;

    k0a<<<1, 256>>>(w1, g1, b1, m1, v1, w2, g2, b2, m2, v2);
    k0b<<<1, 256>>>(w3, g3, b3, m3, v3);
    k1<<<dim3(16, 128), 128>>>(x);
    k2<<<dim3(64, 128), 256>>>();
    k3<<<dim3(32, 128), 256>>>();
    k4<<<128, 128>>>(rms, fc1w, fc1b, fc2w, fc2b, out);
}

// round 5
// speedup vs baseline: 1.7458x; 1.0668x over previous
#include <cuda_runtime.h>

#define EPS 1e-5f
typedef unsigned long long ull;
struct ull2x { ull x, y; };

// Batch-pair interleaved intermediates: lane0=batch 2bp, lane1=batch 2bp+1
static __device__ ull g_buf1u[128 * 16 * 4096];  // stage1 pooled [bp][ch][pos]
static __device__ ull g_buf2u[128 * 32 * 1024];  // stage2 pooled [bp][ch][pos]
static __device__ ull g_partu[128 * 64 * 64];    // stage3 partials [bp][group][ch]

// Pre-packed weights: value duplicated in both lanes (lanes are batches)
static __device__ ull pw1[16 * 17];       // [ch][k]
static __device__ ull psh1[16];
static __device__ ull pw2[16 * 9 * 32];   // [(ci*9+k)*32 + co]
static __device__ ull psh2[32];
static __device__ ull pw3[32 * 5 * 64];   // [(ci*5+k)*64 + co]
static __device__ ull psh3[64];

__device__ __forceinline__ float ht(float x) { return fminf(1.f, fmaxf(-1.f, x)); }
__device__ __forceinline__ float sgn(float x) { return (x > 0.f) ? 1.f : ((x < 0.f) ? -1.f : 0.f); }

__device__ __forceinline__ ull fma2(ull a, ull b, ull c) {
    ull d; asm("fma.rn.f32x2 %0, %1, %2, %3;" : "=l"(d) : "l"(a), "l"(b), "l"(c)); return d;
}
__device__ __forceinline__ ull add2(ull a, ull b) {
    ull d; asm("add.rn.f32x2 %0, %1, %2;" : "=l"(d) : "l"(a), "l"(b)); return d;
}
__device__ __forceinline__ ull pk(float lo, float hi) {
    ull d; asm("mov.b64 %0, {%1, %2};" : "=l"(d) : "f"(lo), "f"(hi)); return d;
}
__device__ __forceinline__ void upk(ull d, float& lo, float& hi) {
    asm("mov.b64 {%0, %1}, %2;" : "=f"(lo), "=f"(hi) : "l"(d));
}

// ---------------------------------------------------------------------------
// k0a: pre-pack stage-1/2 weights (BN scale folded, duplicated lanes) + shifts
// ---------------------------------------------------------------------------
__global__ void k0a(
    const float* __restrict__ w1,
    const float* __restrict__ g1, const float* __restrict__ b1,
    const float* __restrict__ m1, const float* __restrict__ v1,
    const float* __restrict__ w2,
    const float* __restrict__ g2, const float* __restrict__ b2,
    const float* __restrict__ m2, const float* __restrict__ v2)
{
    const int tid = threadIdx.x;
    for (int i = tid; i < 272; i += 256) {
        int ch = i / 17, k = i % 17;
        float s = g1[ch] * rsqrtf(v1[ch] + EPS);
        float v = w1[ch * 17 + k] * s;
        pw1[i] = pk(v, v);
    }
    if (tid < 16) {
        float s = g1[tid] * rsqrtf(v1[tid] + EPS);
        float t = b1[tid] - m1[tid] * s;
        psh1[tid] = pk(t, t);
    }
    for (int i = tid; i < 4608; i += 256) {
        int co = i & 31, r = i >> 5;
        int k = r % 9, ci = r / 9;
        float s = g2[co] * rsqrtf(v2[co] + EPS);
        float v = sgn(w2[co * 144 + ci * 9 + k]) * s;
        pw2[i] = pk(v, v);
    }
    if (tid < 32) {
        float s = g2[tid] * rsqrtf(v2[tid] + EPS);
        float t = b2[tid] - m2[tid] * s;
        psh2[tid] = pk(t, t);
    }
}

// ---------------------------------------------------------------------------
// k0b: pre-pack stage-3 weights + shifts
// ---------------------------------------------------------------------------
__global__ void k0b(
    const float* __restrict__ w3,
    const float* __restrict__ g3, const float* __restrict__ b3,
    const float* __restrict__ m3, const float* __restrict__ v3)
{
    const int tid = threadIdx.x;
    for (int i = tid; i < 10240; i += 256) {
        int co = i & 63, r = i >> 6;
        int k = r % 5, ci = r / 5;
        float s = g3[co] * rsqrtf(v3[co] + EPS);
        float v = sgn(w3[co * 160 + ci * 5 + k]) * s;
        pw3[i] = pk(v, v);
    }
    if (tid < 64) {
        float s = g3[tid] * rsqrtf(v3[tid] + EPS);
        float t = b3[tid] - m3[tid] * s;
        psh3[tid] = pk(t, t);
    }
}

// ---------------------------------------------------------------------------
// Kernel 1: conv1 (1->16, K=17, s=2, p=8) + BN + ht + pool. Batch-pair lanes.
// ---------------------------------------------------------------------------
__global__ __launch_bounds__(128) void k1(const float* __restrict__ x)
{
    __shared__ ull xs[1040];
    __shared__ ull ws[272];
    __shared__ ull sh[16];

    const int bp = blockIdx.y;
    const int p0 = blockIdx.x * 256;
    const int tid = threadIdx.x;

    for (int i = tid; i < 272; i += 128) ws[i] = pw1[i];
    if (tid < 16) sh[tid] = psh1[tid];

    const float* xb0 = x + (2 * bp) * 16384;
    const float* xb1 = xb0 + 16384;
    const int base = 4 * p0 - 8;
    for (int i = tid; i < 1039; i += 128) {
        int gi = base + i;
        xs[i] = (gi >= 0 && gi < 16384) ? pk(xb0[gi], xb1[gi]) : 0ull;
    }
    __syncthreads();

    ull xp[23];
#pragma unroll
    for (int j = 0; j < 11; j++) {
        ull2x t = *(const ull2x*)&xs[8 * tid + 2 * j];
        xp[2 * j] = t.x; xp[2 * j + 1] = t.y;
    }
    xp[22] = xs[8 * tid + 22];

    const int p = p0 + 2 * tid;
#pragma unroll 1
    for (int ch = 0; ch < 16; ch++) {
        ull h2 = sh[ch];
        ull a[4] = {h2, h2, h2, h2};
#pragma unroll
        for (int k = 0; k < 17; k++) {
            ull w = ws[ch * 17 + k];
#pragma unroll
            for (int j = 0; j < 4; j++) a[j] = fma2(w, xp[2 * j + k], a[j]);
        }
        float lo[4], hi[4];
#pragma unroll
        for (int j = 0; j < 4; j++) upk(a[j], lo[j], hi[j]);
        ull2x o;
        o.x = pk(ht(fmaxf(lo[0], lo[1])), ht(fmaxf(hi[0], hi[1])));
        o.y = pk(ht(fmaxf(lo[2], lo[3])), ht(fmaxf(hi[2], hi[3])));
        *(ull2x*)&g_buf1u[(bp * 16 + ch) * 4096 + p] = o;
    }
}

// ---------------------------------------------------------------------------
// Kernel 2: conv2 (16->32, +-s weights, K=9, s=2, p=4) + ht + pool.
// grid (32, 128), 128 thr. Thread (co=tid&15 -> channels co & co+16,
// pq=tid>>4 -> 4 pooled positions). 2ch x 8 conv outs per thread.
// ---------------------------------------------------------------------------
__global__ __launch_bounds__(128) void k2()
{
    __shared__ ull xs2[16 * 136];

    const int bp = blockIdx.y;
    const int p0 = blockIdx.x * 32;
    const int tid = threadIdx.x;
    const int co = tid & 15;
    const int pq = tid >> 4;   // 0..7

    const ull* __restrict__ in = g_buf1u + bp * 16 * 4096;
    const int base = 4 * p0 - 4;
    for (int i = tid; i < 16 * 135; i += 128) {
        int row = i / 135, col = i % 135;
        int gi = base + col;
        xs2[row * 136 + col] = (gi >= 0 && gi < 4096) ? in[row * 4096 + gi] : 0ull;
    }
    __syncthreads();

    ull acc0[8], acc1[8];
    {
        ull h0 = psh2[co], h1 = psh2[co + 16];
#pragma unroll
        for (int j = 0; j < 8; j++) { acc0[j] = h0; acc1[j] = h1; }
    }
    const ull* __restrict__ wp0 = pw2 + co;
    const ull* __restrict__ wp1 = pw2 + co + 16;

#pragma unroll 1
    for (int ci = 0; ci < 16; ci++) {
        ull xp[23];
#pragma unroll
        for (int j = 0; j < 11; j++) {
            ull2x t = *(const ull2x*)&xs2[ci * 136 + 16 * pq + 2 * j];
            xp[2 * j] = t.x; xp[2 * j + 1] = t.y;
        }
        xp[22] = xs2[ci * 136 + 16 * pq + 22];
#pragma unroll
        for (int k = 0; k < 9; k++) {
            ull w0 = wp0[(ci * 9 + k) * 32];
            ull w1 = wp1[(ci * 9 + k) * 32];
#pragma unroll
            for (int j = 0; j < 8; j++) {
                acc0[j] = fma2(w0, xp[2 * j + k], acc0[j]);
                acc1[j] = fma2(w1, xp[2 * j + k], acc1[j]);
            }
        }
    }

    const int pp = p0 + 4 * pq;
    {
        float lo[8], hi[8];
#pragma unroll
        for (int j = 0; j < 8; j++) upk(acc0[j], lo[j], hi[j]);
        ull2x oa, ob;
        oa.x = pk(ht(fmaxf(lo[0], lo[1])), ht(fmaxf(hi[0], hi[1])));
        oa.y = pk(ht(fmaxf(lo[2], lo[3])), ht(fmaxf(hi[2], hi[3])));
        ob.x = pk(ht(fmaxf(lo[4], lo[5])), ht(fmaxf(hi[4], hi[5])));
        ob.y = pk(ht(fmaxf(lo[6], lo[7])), ht(fmaxf(hi[6], hi[7])));
        *(ull2x*)&g_buf2u[(bp * 32 + co) * 1024 + pp] = oa;
        *(ull2x*)&g_buf2u[(bp * 32 + co) * 1024 + pp + 2] = ob;
    }
    {
        float lo[8], hi[8];
#pragma unroll
        for (int j = 0; j < 8; j++) upk(acc1[j], lo[j], hi[j]);
        ull2x oa, ob;
        oa.x = pk(ht(fmaxf(lo[0], lo[1])), ht(fmaxf(hi[0], hi[1])));
        oa.y = pk(ht(fmaxf(lo[2], lo[3])), ht(fmaxf(hi[2], hi[3])));
        ob.x = pk(ht(fmaxf(lo[4], lo[5])), ht(fmaxf(hi[4], hi[5])));
        ob.y = pk(ht(fmaxf(lo[6], lo[7])), ht(fmaxf(hi[6], hi[7])));
        *(ull2x*)&g_buf2u[(bp * 32 + co + 16) * 1024 + pp] = oa;
        *(ull2x*)&g_buf2u[(bp * 32 + co + 16) * 1024 + pp + 2] = ob;
    }
}

// ---------------------------------------------------------------------------
// Kernel 3: conv3 (32->64, +-s weights, K=5, s=2, p=2) + ht + pool + partials.
// grid (16, 128), 128 thr. Thread (co=tid&31 -> channels co & co+32,
// pq=tid>>5 -> 4 pooled positions). 2ch x 8 conv outs per thread.
// ---------------------------------------------------------------------------
__global__ __launch_bounds__(128) void k3()
{
    __shared__ ull xs3[32 * 68];

    const int bp = blockIdx.y;
    const int p0 = blockIdx.x * 16;
    const int tid = threadIdx.x;
    const int co = tid & 31;
    const int pq = tid >> 5;   // 0..3

    const ull* __restrict__ in = g_buf2u + bp * 32 * 1024;
    const int base = 4 * p0 - 2;
    for (int i = tid; i < 32 * 67; i += 128) {
        int row = i / 67, col = i % 67;
        int gi = base + col;
        xs3[row * 68 + col] = (gi >= 0 && gi < 1024) ? in[row * 1024 + gi] : 0ull;
    }
    __syncthreads();

    ull acc0[8], acc1[8];
    {
        ull h0 = psh3[co], h1 = psh3[co + 32];
#pragma unroll
        for (int j = 0; j < 8; j++) { acc0[j] = h0; acc1[j] = h1; }
    }
    const ull* __restrict__ wp0 = pw3 + co;
    const ull* __restrict__ wp1 = pw3 + co + 32;

#pragma unroll 1
    for (int ci = 0; ci < 32; ci++) {
        ull xp[19];
#pragma unroll
        for (int j = 0; j < 9; j++) {
            ull2x t = *(const ull2x*)&xs3[ci * 68 + 16 * pq + 2 * j];
            xp[2 * j] = t.x; xp[2 * j + 1] = t.y;
        }
        xp[18] = xs3[ci * 68 + 16 * pq + 18];
#pragma unroll
        for (int k = 0; k < 5; k++) {
            ull w0 = wp0[(ci * 5 + k) * 64];
            ull w1 = wp1[(ci * 5 + k) * 64];
#pragma unroll
            for (int j = 0; j < 8; j++) {
                acc0[j] = fma2(w0, xp[2 * j + k], acc0[j]);
                acc1[j] = fma2(w1, xp[2 * j + k], acc1[j]);
            }
        }
    }

    const int grp = blockIdx.x * 4 + pq;   // 0..63
    {
        float lo[8], hi[8];
#pragma unroll
        for (int j = 0; j < 8; j++) upk(acc0[j], lo[j], hi[j]);
        float s0 = ht(fmaxf(lo[0], lo[1])) + ht(fmaxf(lo[2], lo[3]))
                 + ht(fmaxf(lo[4], lo[5])) + ht(fmaxf(lo[6], lo[7]));
        float s1 = ht(fmaxf(hi[0], hi[1])) + ht(fmaxf(hi[2], hi[3]))
                 + ht(fmaxf(hi[4], hi[5])) + ht(fmaxf(hi[6], hi[7]));
        g_partu[(bp * 64 + grp) * 64 + co] = pk(s0, s1);
    }
    {
        float lo[8], hi[8];
#pragma unroll
        for (int j = 0; j < 8; j++) upk(acc1[j], lo[j], hi[j]);
        float s0 = ht(fmaxf(lo[0], lo[1])) + ht(fmaxf(lo[2], lo[3]))
                 + ht(fmaxf(lo[4], lo[5])) + ht(fmaxf(lo[6], lo[7]));
        float s1 = ht(fmaxf(hi[0], hi[1])) + ht(fmaxf(hi[2], hi[3]))
                 + ht(fmaxf(hi[4], hi[5])) + ht(fmaxf(hi[6], hi[7]));
        g_partu[(bp * 64 + grp) * 64 + co + 32] = pk(s0, s1);
    }
}

// ---------------------------------------------------------------------------
// Kernel 4: reduce partials -> mean, concat rms, fc1 + ht, fc2. Per batch-pair.
// ---------------------------------------------------------------------------
__global__ __launch_bounds__(128) void k4(
    const float* __restrict__ rms,
    const float* __restrict__ fc1w, const float* __restrict__ fc1b,
    const float* __restrict__ fc2w, const float* __restrict__ fc2b,
    float* __restrict__ out)
{
    __shared__ float comb[2][65];
    __shared__ float h1[2][32];
    const int bp = blockIdx.x;
    const int tid = threadIdx.x;

    if (tid < 64) {
        ull s = 0ull;
        const ull* basep = g_partu + bp * 64 * 64 + tid;
#pragma unroll
        for (int g = 0; g < 64; g++) s = add2(s, basep[g * 64]);
        float a, b; upk(s, a, b);
        comb[0][tid] = a * (1.f / 256.f);
        comb[1][tid] = b * (1.f / 256.f);
    }
    if (tid == 64) { comb[0][64] = rms[2 * bp]; }
    if (tid == 65) { comb[1][64] = rms[2 * bp + 1]; }
    __syncthreads();

    const int half = tid >> 6;
    const int t = tid & 63;
    if (t < 32) {
        float a = fc1b[t];
        const float* wr = fc1w + t * 65;
        const float* cb = comb[half];
#pragma unroll
        for (int i = 0; i < 65; i++) a = fmaf(cb[i], wr[i], a);
        h1[half][t] = ht(a);
    }
    __syncthreads();

    if (t < 2) {
        float a = fc2b[t];
        const float* wr = fc2w + t * 32;
        const float* hh = h1[half];
#pragma unroll
        for (int i = 0; i < 32; i++) a = fmaf(hh[i], wr[i], a);
        out[(2 * bp + half) * 2 + t] = a;
    }
}

// ---------------------------------------------------------------------------
extern "C" void kernel_launch(void* const* d_in, const int* in_sizes, int n_in,
                              void* d_out, int out_size)
{
    const float* x     = (const float*)d_in[0];
    const float* rms   = (const float*)d_in[1];
    const float* w1    = (const float*)d_in[2];
    const float* g1    = (const float*)d_in[3];
    const float* b1    = (const float*)d_in[4];
    const float* m1    = (const float*)d_in[5];
    const float* v1    = (const float*)d_in[6];
    const float* w2    = (const float*)d_in[7];
    const float* g2    = (const float*)d_in[8];
    const float* b2    = (const float*)d_in[9];
    const float* m2    = (const float*)d_in[10];
    const float* v2    = (const float*)d_in[11];
    const float* w3    = (const float*)d_in[12];
    const float* g3    = (const float*)d_in[13];
    const float* b3    = (const float*)d_in[14];
    const float* m3    = (const float*)d_in[15];
    const float* v3    = (const float*)d_in[16];
    const float* fc1w  = (const float*)d_in[17];
    const float* fc1b  = (const float*)d_in[18];
    const float* fc2w  = (const float*)d_in[19];
    const float* fc2b  = (const float*)d_in[20];
    float* out = (float*)d_out;

    k0a<<<1, 256>>>(w1, g1, b1, m1, v1, w2, g2, b2, m2, v2);
    k0b<<<1, 256>>>(w3, g3, b3, m3, v3);
    k1<<<dim3(16, 128), 128>>>(x);
    k2<<<dim3(32, 128), 128>>>();
    k3<<<dim3(16, 128), 128>>>();
    k4<<<128, 128>>>(rms, fc1w, fc1b, fc2w, fc2b, out);
}

// round 6
// speedup vs baseline: 1.8115x; 1.0376x over previous
#include <cuda_runtime.h>

#define EPS 1e-5f
typedef unsigned long long ull;
struct ull2x { ull x, y; };

// Batch-pair interleaved intermediates: lane0=batch 2bp, lane1=batch 2bp+1
static __device__ ull g_buf1u[128 * 16 * 4096];  // stage1 pooled [bp][ch][pos]
static __device__ ull g_buf2u[128 * 32 * 1024];  // stage2 pooled [bp][ch][pos]
static __device__ ull g_partu[128 * 64 * 64];    // stage3 partials [bp][group][ch]

// Pre-packed weights: value duplicated in both lanes (lanes are batches)
static __device__ ull pw1[16 * 17];       // [ch][k]
static __device__ ull psh1[16];
static __device__ ull pw2[16 * 9 * 32];   // [(ci*9+k)*32 + co]
static __device__ ull psh2[32];
static __device__ ull pw3[32 * 5 * 64];   // [(ci*5+k)*64 + co]
static __device__ ull psh3[64];

__device__ __forceinline__ float ht(float x) { return fminf(1.f, fmaxf(-1.f, x)); }
__device__ __forceinline__ float sgn(float x) { return (x > 0.f) ? 1.f : ((x < 0.f) ? -1.f : 0.f); }

__device__ __forceinline__ ull fma2(ull a, ull b, ull c) {
    ull d; asm("fma.rn.f32x2 %0, %1, %2, %3;" : "=l"(d) : "l"(a), "l"(b), "l"(c)); return d;
}
__device__ __forceinline__ ull add2(ull a, ull b) {
    ull d; asm("add.rn.f32x2 %0, %1, %2;" : "=l"(d) : "l"(a), "l"(b)); return d;
}
__device__ __forceinline__ ull pk(float lo, float hi) {
    ull d; asm("mov.b64 %0, {%1, %2};" : "=l"(d) : "f"(lo), "f"(hi)); return d;
}
__device__ __forceinline__ void upk(ull d, float& lo, float& hi) {
    asm("mov.b64 {%0, %1}, %2;" : "=f"(lo), "=f"(hi) : "l"(d));
}

// ---------------------------------------------------------------------------
// k0a / k0b: weight pre-pack (BN scale folded, lanes duplicated)
// ---------------------------------------------------------------------------
__global__ void k0a(
    const float* __restrict__ w1,
    const float* __restrict__ g1, const float* __restrict__ b1,
    const float* __restrict__ m1, const float* __restrict__ v1,
    const float* __restrict__ w2,
    const float* __restrict__ g2, const float* __restrict__ b2,
    const float* __restrict__ m2, const float* __restrict__ v2)
{
    const int tid = threadIdx.x;
    for (int i = tid; i < 272; i += 256) {
        int ch = i / 17, k = i % 17;
        float s = g1[ch] * rsqrtf(v1[ch] + EPS);
        float v = w1[ch * 17 + k] * s;
        pw1[i] = pk(v, v);
    }
    if (tid < 16) {
        float s = g1[tid] * rsqrtf(v1[tid] + EPS);
        float t = b1[tid] - m1[tid] * s;
        psh1[tid] = pk(t, t);
    }
    for (int i = tid; i < 4608; i += 256) {
        int co = i & 31, r = i >> 5;
        int k = r % 9, ci = r / 9;
        float s = g2[co] * rsqrtf(v2[co] + EPS);
        float v = sgn(w2[co * 144 + ci * 9 + k]) * s;
        pw2[i] = pk(v, v);
    }
    if (tid < 32) {
        float s = g2[tid] * rsqrtf(v2[tid] + EPS);
        float t = b2[tid] - m2[tid] * s;
        psh2[tid] = pk(t, t);
    }
}

__global__ void k0b(
    const float* __restrict__ w3,
    const float* __restrict__ g3, const float* __restrict__ b3,
    const float* __restrict__ m3, const float* __restrict__ v3)
{
    const int tid = threadIdx.x;
    for (int i = tid; i < 10240; i += 256) {
        int co = i & 63, r = i >> 6;
        int k = r % 5, ci = r / 5;
        float s = g3[co] * rsqrtf(v3[co] + EPS);
        float v = sgn(w3[co * 160 + ci * 5 + k]) * s;
        pw3[i] = pk(v, v);
    }
    if (tid < 64) {
        float s = g3[tid] * rsqrtf(v3[tid] + EPS);
        float t = b3[tid] - m3[tid] * s;
        psh3[tid] = pk(t, t);
    }
}

// ---------------------------------------------------------------------------
// Kernel 1: conv1 (1->16, K=17, s=2, p=8) + BN + ht + pool. Batch-pair lanes.
// ---------------------------------------------------------------------------
__global__ __launch_bounds__(128) void k1(const float* __restrict__ x)
{
    __shared__ ull xs[1040];
    __shared__ ull ws[272];
    __shared__ ull sh[16];

    const int bp = blockIdx.y;
    const int p0 = blockIdx.x * 256;
    const int tid = threadIdx.x;

    for (int i = tid; i < 272; i += 128) ws[i] = pw1[i];
    if (tid < 16) sh[tid] = psh1[tid];

    const float* xb0 = x + (2 * bp) * 16384;
    const float* xb1 = xb0 + 16384;
    const int base = 4 * p0 - 8;
    for (int i = tid; i < 1039; i += 128) {
        int gi = base + i;
        xs[i] = (gi >= 0 && gi < 16384) ? pk(xb0[gi], xb1[gi]) : 0ull;
    }
    __syncthreads();

    ull xp[23];
#pragma unroll
    for (int j = 0; j < 11; j++) {
        ull2x t = *(const ull2x*)&xs[8 * tid + 2 * j];
        xp[2 * j] = t.x; xp[2 * j + 1] = t.y;
    }
    xp[22] = xs[8 * tid + 22];

    const int p = p0 + 2 * tid;
#pragma unroll 1
    for (int ch = 0; ch < 16; ch++) {
        ull h2 = sh[ch];
        ull a[4] = {h2, h2, h2, h2};
#pragma unroll
        for (int k = 0; k < 17; k++) {
            ull w = ws[ch * 17 + k];
#pragma unroll
            for (int j = 0; j < 4; j++) a[j] = fma2(w, xp[2 * j + k], a[j]);
        }
        float lo[4], hi[4];
#pragma unroll
        for (int j = 0; j < 4; j++) upk(a[j], lo[j], hi[j]);
        ull2x o;
        o.x = pk(ht(fmaxf(lo[0], lo[1])), ht(fmaxf(hi[0], hi[1])));
        o.y = pk(ht(fmaxf(lo[2], lo[3])), ht(fmaxf(hi[2], hi[3])));
        *(ull2x*)&g_buf1u[(bp * 16 + ch) * 4096 + p] = o;
    }
}

// ---------------------------------------------------------------------------
// Kernel 2: conv2 (16->32) + ht + pool. Software-pipelined (double-buffered
// input window). Thread (co=tid&15 -> ch co & co+16, pq=tid>>4 -> 4 pooled).
// ---------------------------------------------------------------------------
#define K2_LOAD(XP, CI)                                                        \
    {                                                                          \
        const ull* rowp = &xs2[(CI) * 136 + 16 * pq];                          \
        _Pragma("unroll")                                                      \
        for (int j = 0; j < 11; j++) {                                         \
            ull2x t = *(const ull2x*)&rowp[2 * j];                             \
            XP[2 * j] = t.x; XP[2 * j + 1] = t.y;                              \
        }                                                                      \
        XP[22] = rowp[22];                                                     \
    }

#define K2_FMA(XP, CI)                                                         \
    {                                                                          \
        _Pragma("unroll")                                                      \
        for (int k = 0; k < 9; k++) {                                          \
            ull w0 = wp0[((CI) * 9 + k) * 32];                                 \
            ull w1 = wp1[((CI) * 9 + k) * 32];                                 \
            _Pragma("unroll")                                                  \
            for (int j = 0; j < 8; j++) {                                      \
                acc0[j] = fma2(w0, XP[2 * j + k], acc0[j]);                    \
                acc1[j] = fma2(w1, XP[2 * j + k], acc1[j]);                    \
            }                                                                  \
        }                                                                      \
    }

__global__ __launch_bounds__(128) void k2()
{
    __shared__ ull xs2[16 * 136];

    const int bp = blockIdx.y;
    const int p0 = blockIdx.x * 32;
    const int tid = threadIdx.x;
    const int co = tid & 15;
    const int pq = tid >> 4;   // 0..7

    const ull* __restrict__ in = g_buf1u + bp * 16 * 4096;
    const int base = 4 * p0 - 4;
    for (int i = tid; i < 16 * 135; i += 128) {
        int row = i / 135, col = i % 135;
        int gi = base + col;
        xs2[row * 136 + col] = (gi >= 0 && gi < 4096) ? in[row * 4096 + gi] : 0ull;
    }
    __syncthreads();

    ull acc0[8], acc1[8];
    {
        ull h0 = psh2[co], h1 = psh2[co + 16];
#pragma unroll
        for (int j = 0; j < 8; j++) { acc0[j] = h0; acc1[j] = h1; }
    }
    const ull* __restrict__ wp0 = pw2 + co;
    const ull* __restrict__ wp1 = pw2 + co + 16;

    ull xpA[23], xpB[23];
    K2_LOAD(xpA, 0)
#pragma unroll 1
    for (int ci = 0; ci < 16; ci += 2) {
        K2_LOAD(xpB, ci + 1)
        K2_FMA(xpA, ci)
        if (ci + 2 < 16) K2_LOAD(xpA, ci + 2)
        K2_FMA(xpB, ci + 1)
    }

    const int pp = p0 + 4 * pq;
    {
        float lo[8], hi[8];
#pragma unroll
        for (int j = 0; j < 8; j++) upk(acc0[j], lo[j], hi[j]);
        ull2x oa, ob;
        oa.x = pk(ht(fmaxf(lo[0], lo[1])), ht(fmaxf(hi[0], hi[1])));
        oa.y = pk(ht(fmaxf(lo[2], lo[3])), ht(fmaxf(hi[2], hi[3])));
        ob.x = pk(ht(fmaxf(lo[4], lo[5])), ht(fmaxf(hi[4], hi[5])));
        ob.y = pk(ht(fmaxf(lo[6], lo[7])), ht(fmaxf(hi[6], hi[7])));
        *(ull2x*)&g_buf2u[(bp * 32 + co) * 1024 + pp] = oa;
        *(ull2x*)&g_buf2u[(bp * 32 + co) * 1024 + pp + 2] = ob;
    }
    {
        float lo[8], hi[8];
#pragma unroll
        for (int j = 0; j < 8; j++) upk(acc1[j], lo[j], hi[j]);
        ull2x oa, ob;
        oa.x = pk(ht(fmaxf(lo[0], lo[1])), ht(fmaxf(hi[0], hi[1])));
        oa.y = pk(ht(fmaxf(lo[2], lo[3])), ht(fmaxf(hi[2], hi[3])));
        ob.x = pk(ht(fmaxf(lo[4], lo[5])), ht(fmaxf(hi[4], hi[5])));
        ob.y = pk(ht(fmaxf(lo[6], lo[7])), ht(fmaxf(hi[6], hi[7])));
        *(ull2x*)&g_buf2u[(bp * 32 + co + 16) * 1024 + pp] = oa;
        *(ull2x*)&g_buf2u[(bp * 32 + co + 16) * 1024 + pp + 2] = ob;
    }
}

// ---------------------------------------------------------------------------
// Kernel 3: conv3 (32->64) + ht + pool + partials. Software-pipelined.
// Thread (co=tid&31 -> ch co & co+32, pq=tid>>5 -> 4 pooled positions).
// ---------------------------------------------------------------------------
#define K3_LOAD(XP, CI)                                                        \
    {                                                                          \
        const ull* rowp = &xs3[(CI) * 68 + 16 * pq];                           \
        _Pragma("unroll")                                                      \
        for (int j = 0; j < 9; j++) {                                          \
            ull2x t = *(const ull2x*)&rowp[2 * j];                             \
            XP[2 * j] = t.x; XP[2 * j + 1] = t.y;                              \
        }                                                                      \
        XP[18] = rowp[18];                                                     \
    }

#define K3_FMA(XP, CI)                                                         \
    {                                                                          \
        _Pragma("unroll")                                                      \
        for (int k = 0; k < 5; k++) {                                          \
            ull w0 = wp0[((CI) * 5 + k) * 64];                                 \
            ull w1 = wp1[((CI) * 5 + k) * 64];                                 \
            _Pragma("unroll")                                                  \
            for (int j = 0; j < 8; j++) {                                      \
                acc0[j] = fma2(w0, XP[2 * j + k], acc0[j]);                    \
                acc1[j] = fma2(w1, XP[2 * j + k], acc1[j]);                    \
            }                                                                  \
        }                                                                      \
    }

__global__ __launch_bounds__(128) void k3()
{
    __shared__ ull xs3[32 * 68];

    const int bp = blockIdx.y;
    const int p0 = blockIdx.x * 16;
    const int tid = threadIdx.x;
    const int co = tid & 31;
    const int pq = tid >> 5;   // 0..3

    const ull* __restrict__ in = g_buf2u + bp * 32 * 1024;
    const int base = 4 * p0 - 2;
    for (int i = tid; i < 32 * 67; i += 128) {
        int row = i / 67, col = i % 67;
        int gi = base + col;
        xs3[row * 68 + col] = (gi >= 0 && gi < 1024) ? in[row * 1024 + gi] : 0ull;
    }
    __syncthreads();

    ull acc0[8], acc1[8];
    {
        ull h0 = psh3[co], h1 = psh3[co + 32];
#pragma unroll
        for (int j = 0; j < 8; j++) { acc0[j] = h0; acc1[j] = h1; }
    }
    const ull* __restrict__ wp0 = pw3 + co;
    const ull* __restrict__ wp1 = pw3 + co + 32;

    ull xpA[19], xpB[19];
    K3_LOAD(xpA, 0)
#pragma unroll 1
    for (int ci = 0; ci < 32; ci += 2) {
        K3_LOAD(xpB, ci + 1)
        K3_FMA(xpA, ci)
        if (ci + 2 < 32) K3_LOAD(xpA, ci + 2)
        K3_FMA(xpB, ci + 1)
    }

    const int grp = blockIdx.x * 4 + pq;   // 0..63
    {
        float lo[8], hi[8];
#pragma unroll
        for (int j = 0; j < 8; j++) upk(acc0[j], lo[j], hi[j]);
        float s0 = ht(fmaxf(lo[0], lo[1])) + ht(fmaxf(lo[2], lo[3]))
                 + ht(fmaxf(lo[4], lo[5])) + ht(fmaxf(lo[6], lo[7]));
        float s1 = ht(fmaxf(hi[0], hi[1])) + ht(fmaxf(hi[2], hi[3]))
                 + ht(fmaxf(hi[4], hi[5])) + ht(fmaxf(hi[6], hi[7]));
        g_partu[(bp * 64 + grp) * 64 + co] = pk(s0, s1);
    }
    {
        float lo[8], hi[8];
#pragma unroll
        for (int j = 0; j < 8; j++) upk(acc1[j], lo[j], hi[j]);
        float s0 = ht(fmaxf(lo[0], lo[1])) + ht(fmaxf(lo[2], lo[3]))
                 + ht(fmaxf(lo[4], lo[5])) + ht(fmaxf(lo[6], lo[7]));
        float s1 = ht(fmaxf(hi[0], hi[1])) + ht(fmaxf(hi[2], hi[3]))
                 + ht(fmaxf(hi[4], hi[5])) + ht(fmaxf(hi[6], hi[7]));
        g_partu[(bp * 64 + grp) * 64 + co + 32] = pk(s0, s1);
    }
}

// ---------------------------------------------------------------------------
// Kernel 4: reduce partials -> mean, concat rms, fc1 + ht, fc2. Per batch-pair.
// ---------------------------------------------------------------------------
__global__ __launch_bounds__(128) void k4(
    const float* __restrict__ rms,
    const float* __restrict__ fc1w, const float* __restrict__ fc1b,
    const float* __restrict__ fc2w, const float* __restrict__ fc2b,
    float* __restrict__ out)
{
    __shared__ float comb[2][65];
    __shared__ float h1[2][32];
    const int bp = blockIdx.x;
    const int tid = threadIdx.x;

    if (tid < 64) {
        ull s = 0ull;
        const ull* basep = g_partu + bp * 64 * 64 + tid;
#pragma unroll
        for (int g = 0; g < 64; g++) s = add2(s, basep[g * 64]);
        float a, b; upk(s, a, b);
        comb[0][tid] = a * (1.f / 256.f);
        comb[1][tid] = b * (1.f / 256.f);
    }
    if (tid == 64) { comb[0][64] = rms[2 * bp]; }
    if (tid == 65) { comb[1][64] = rms[2 * bp + 1]; }
    __syncthreads();

    const int half = tid >> 6;
    const int t = tid & 63;
    if (t < 32) {
        float a = fc1b[t];
        const float* wr = fc1w + t * 65;
        const float* cb = comb[half];
#pragma unroll
        for (int i = 0; i < 65; i++) a = fmaf(cb[i], wr[i], a);
        h1[half][t] = ht(a);
    }
    __syncthreads();

    if (t < 2) {
        float a = fc2b[t];
        const float* wr = fc2w + t * 32;
        const float* hh = h1[half];
#pragma unroll
        for (int i = 0; i < 32; i++) a = fmaf(hh[i], wr[i], a);
        out[(2 * bp + half) * 2 + t] = a;
    }
}

// ---------------------------------------------------------------------------
extern "C" void kernel_launch(void* const* d_in, const int* in_sizes, int n_in,
                              void* d_out, int out_size)
{
    const float* x     = (const float*)d_in[0];
    const float* rms   = (const float*)d_in[1];
    const float* w1    = (const float*)d_in[2];
    const float* g1    = (const float*)d_in[3];
    const float* b1    = (const float*)d_in[4];
    const float* m1    = (const float*)d_in[5];
    const float* v1    = (const float*)d_in[6];
    const float* w2    = (const float*)d_in[7];
    const float* g2    = (const float*)d_in[8];
    const float* b2    = (const float*)d_in[9];
    const float* m2    = (const float*)d_in[10];
    const float* v2    = (const float*)d_in[11];
    const float* w3    = (const float*)d_in[12];
    const float* g3    = (const float*)d_in[13];
    const float* b3    = (const float*)d_in[14];
    const float* m3    = (const float*)d_in[15];
    const float* v3    = (const float*)d_in[16];
    const float* fc1w  = (const float*)d_in[17];
    const float* fc1b  = (const float*)d_in[18];
    const float* fc2w  = (const float*)d_in[19];
    const float* fc2b  = (const float*)d_in[20];
    float* out = (float*)d_out;

    k0a<<<1, 256>>>(w1, g1, b1, m1, v1, w2, g2, b2, m2, v2);
    k0b<<<1, 256>>>(w3, g3, b3, m3, v3);
    k1<<<dim3(16, 128), 128>>>(x);
    k2<<<dim3(32, 128), 128>>>();
    k3<<<dim3(16, 128), 128>>>();
    k4<<<128, 128>>>(rms, fc1w, fc1b, fc2w, fc2b, out);
}

// round 9
// speedup vs baseline: 3.3415x; 1.8446x over previous
#include <cuda_runtime.h>
#include <cuda_bf16.h>
#include <cstdint>

#define EPS 1e-5f
typedef unsigned long long ull;
struct ull2x { ull x, y; };

// ---------------------------------------------------------------------------
// Buffers
// ---------------------------------------------------------------------------
static __device__ float g_buf1f[256 * 16 * 4096];  // stage1 out [b][ch][pos]
static __device__ float g_buf2f[256 * 1024 * 32];  // stage2 out [b][pos][ch]
static __device__ float g_buf3f[256 * 256 * 64];   // stage3 pooled ht [b][pos][ch]

// k1 packed weights (batch-pair lanes)
static __device__ ull pw1[16 * 17];
static __device__ ull psh1[16];

// BN epilogue params for stages 2/3
static __device__ float psc2f[32], pshf2[32];
static __device__ float psc3f[64], pshf3[64];

// B fragments in mma.m16n8k16 per-lane layout: [kc][nt][lane] -> uint2
static __device__ uint2 gB2frag[9 * 4 * 32];    // conv2: K=144, N=32
static __device__ uint2 gB3frag[10 * 8 * 32];   // conv3: K=160, N=64

__device__ __forceinline__ float ht(float x) { return fminf(1.f, fmaxf(-1.f, x)); }
__device__ __forceinline__ float sgn(float x) { return (x > 0.f) ? 1.f : ((x < 0.f) ? -1.f : 0.f); }

__device__ __forceinline__ ull fma2(ull a, ull b, ull c) {
    ull d; asm("fma.rn.f32x2 %0, %1, %2, %3;" : "=l"(d) : "l"(a), "l"(b), "l"(c)); return d;
}
__device__ __forceinline__ ull pk(float lo, float hi) {
    ull d; asm("mov.b64 %0, {%1, %2};" : "=l"(d) : "f"(lo), "f"(hi)); return d;
}
__device__ __forceinline__ void upk(ull d, float& lo, float& hi) {
    asm("mov.b64 {%0, %1}, %2;" : "=f"(lo), "=f"(hi) : "l"(d));
}

// pack two f32 -> bf16x2 (lo in low half)
__device__ __forceinline__ uint32_t cvt2bf(float lo, float hi) {
    uint32_t d; asm("cvt.rn.bf16x2.f32 %0, %1, %2;" : "=r"(d) : "f"(hi), "f"(lo)); return d;
}
__device__ __forceinline__ float bf_lo(uint32_t h) { return __uint_as_float(h << 16); }
__device__ __forceinline__ float bf_hi(uint32_t h) { return __uint_as_float(h & 0xffff0000u); }

// mma.sync m16n8k16 row.col f32.bf16.bf16.f32, D accumulates in place
__device__ __forceinline__ void mma16816(float* d, uint32_t a0, uint32_t a1,
                                         uint32_t a2, uint32_t a3,
                                         uint32_t b0, uint32_t b1) {
    asm volatile(
        "mma.sync.aligned.m16n8k16.row.col.f32.bf16.bf16.f32 "
        "{%0,%1,%2,%3}, {%4,%5,%6,%7}, {%8,%9}, {%0,%1,%2,%3};"
        : "+f"(d[0]), "+f"(d[1]), "+f"(d[2]), "+f"(d[3])
        : "r"(a0), "r"(a1), "r"(a2), "r"(a3), "r"(b0), "r"(b1));
}

// ---------------------------------------------------------------------------
// k0a: k1 weight pack + stage2 BN params + B2 fragments
// ---------------------------------------------------------------------------
__global__ void k0a(
    const float* __restrict__ w1,
    const float* __restrict__ g1, const float* __restrict__ b1,
    const float* __restrict__ m1, const float* __restrict__ v1,
    const float* __restrict__ w2,
    const float* __restrict__ g2, const float* __restrict__ b2,
    const float* __restrict__ m2, const float* __restrict__ v2)
{
    const int tid = threadIdx.x;
    for (int i = tid; i < 272; i += 256) {
        int ch = i / 17, k = i % 17;
        float s = g1[ch] * rsqrtf(v1[ch] + EPS);
        float v = w1[ch * 17 + k] * s;
        pw1[i] = pk(v, v);
    }
    if (tid < 16) {
        float s = g1[tid] * rsqrtf(v1[tid] + EPS);
        float t = b1[tid] - m1[tid] * s;
        psh1[tid] = pk(t, t);
    }
    if (tid < 32) {
        float s = g2[tid] * rsqrtf(v2[tid] + EPS);
        psc2f[tid] = s;
        pshf2[tid] = b2[tid] - m2[tid] * s;
    }
    // B2 fragments: B[k][n] = sgn(w2[n][k/9... ]), col-major mma layout
    for (int i = tid; i < 9 * 4 * 32; i += 256) {
        int kc = i >> 7;             // /128
        int rem = i & 127;
        int nt = rem >> 5;
        int l = rem & 31;
        int co = nt * 8 + (l >> 2);
        int k0 = kc * 16 + 2 * (l & 3);
        float v[4];
#pragma unroll
        for (int j = 0; j < 4; j++) {
            int e = k0 + (j >> 1) * 8 + (j & 1);
            int ci = e / 9, kk = e % 9;
            v[j] = sgn(w2[co * 144 + ci * 9 + kk]);
        }
        uint2 r;
        r.x = cvt2bf(v[0], v[1]);
        r.y = cvt2bf(v[2], v[3]);
        gB2frag[i] = r;
    }
}

// ---------------------------------------------------------------------------
// k0b: stage3 BN params + B3 fragments
// ---------------------------------------------------------------------------
__global__ void k0b(
    const float* __restrict__ w3,
    const float* __restrict__ g3, const float* __restrict__ b3,
    const float* __restrict__ m3, const float* __restrict__ v3)
{
    const int tid = threadIdx.x;
    if (tid < 64) {
        float s = g3[tid] * rsqrtf(v3[tid] + EPS);
        psc3f[tid] = s;
        pshf3[tid] = b3[tid] - m3[tid] * s;
    }
    for (int i = tid; i < 10 * 8 * 32; i += 256) {
        int kc = i >> 8;             // /256
        int rem = i & 255;
        int nt = rem >> 5;
        int l = rem & 31;
        int co = nt * 8 + (l >> 2);
        int k0 = kc * 16 + 2 * (l & 3);
        float v[4];
#pragma unroll
        for (int j = 0; j < 4; j++) {
            int e = k0 + (j >> 1) * 8 + (j & 1);
            int ci = e / 5, kk = e % 5;
            v[j] = sgn(w3[co * 160 + ci * 5 + kk]);
        }
        uint2 r;
        r.x = cvt2bf(v[0], v[1]);
        r.y = cvt2bf(v[2], v[3]);
        gB3frag[i] = r;
    }
}

// ---------------------------------------------------------------------------
// Kernel 1: conv1 (1->16, K=17, s=2, p=8) + BN + ht + pool. FFMA2 batch-pair.
// ---------------------------------------------------------------------------
__global__ __launch_bounds__(128) void k1(const float* __restrict__ x)
{
    __shared__ ull xs[1040];
    __shared__ ull ws[272];
    __shared__ ull sh[16];

    const int bp = blockIdx.y;
    const int p0 = blockIdx.x * 256;
    const int tid = threadIdx.x;

    for (int i = tid; i < 272; i += 128) ws[i] = pw1[i];
    if (tid < 16) sh[tid] = psh1[tid];

    const float* xb0 = x + (2 * bp) * 16384;
    const float* xb1 = xb0 + 16384;
    const int base = 4 * p0 - 8;
    for (int i = tid; i < 1039; i += 128) {
        int gi = base + i;
        xs[i] = (gi >= 0 && gi < 16384) ? pk(xb0[gi], xb1[gi]) : 0ull;
    }
    __syncthreads();

    ull xp[23];
#pragma unroll
    for (int j = 0; j < 11; j++) {
        ull2x t = *(const ull2x*)&xs[8 * tid + 2 * j];
        xp[2 * j] = t.x; xp[2 * j + 1] = t.y;
    }
    xp[22] = xs[8 * tid + 22];

    const int p = p0 + 2 * tid;
#pragma unroll 1
    for (int ch = 0; ch < 16; ch++) {
        ull h2 = sh[ch];
        ull a[4] = {h2, h2, h2, h2};
#pragma unroll
        for (int k = 0; k < 17; k++) {
            ull w = ws[ch * 17 + k];
#pragma unroll
            for (int j = 0; j < 4; j++) a[j] = fma2(w, xp[2 * j + k], a[j]);
        }
        float lo[4], hi[4];
#pragma unroll
        for (int j = 0; j < 4; j++) upk(a[j], lo[j], hi[j]);
        float2 o0, o1;
        o0.x = ht(fmaxf(lo[0], lo[1])); o0.y = ht(fmaxf(lo[2], lo[3]));
        o1.x = ht(fmaxf(hi[0], hi[1])); o1.y = ht(fmaxf(hi[2], hi[3]));
        *(float2*)&g_buf1f[((2 * bp) * 16 + ch) * 4096 + p] = o0;
        *(float2*)&g_buf1f[((2 * bp + 1) * 16 + ch) * 4096 + p] = o1;
    }
}

// ---------------------------------------------------------------------------
// Kernel 2: conv2 (16->32) via mma.sync bf16 (2-way split) + BN + ht + pool.
// Block: 128 conv positions x 32 channels, K = 144. grid (16, 256), 128 thr.
// xs[ci][col] fp32, col = 2*row + k. D staged to smem (aliased) for epilogue.
// ---------------------------------------------------------------------------
__global__ __launch_bounds__(128) void k2()
{
    __shared__ float smem_pool[16 * 264];   // 16.5 KB; reused as D (128*32)

    const int tile = blockIdx.x;   // 0..15
    const int b = blockIdx.y;
    const int tid = threadIdx.x;
    const int w = tid >> 5, l = tid & 31;
    const int g = l >> 2, t = l & 3;

    // Stage input slab
    const float* in = g_buf1f + b * 16 * 4096;
    const int base = tile * 256 - 4;
    for (int i = tid; i < 16 * 263; i += 128) {
        int row = i / 263, col = i % 263;
        int gi = base + col;
        smem_pool[row * 264 + col] = (gi >= 0 && gi < 4096) ? in[row * 4096 + gi] : 0.f;
    }
    __syncthreads();

    float D[2][4][4];
#pragma unroll
    for (int mt = 0; mt < 2; mt++)
#pragma unroll
        for (int nt = 0; nt < 4; nt++)
#pragma unroll
            for (int j = 0; j < 4; j++) D[mt][nt][j] = 0.f;

    const int r0c = 2 * (w * 32 + g);   // col offset for row (x2), mt adds 32, +16 for row+8

#pragma unroll 1
    for (int kc = 0; kc < 9; kc++) {
        uint2 Bf[4];
#pragma unroll
        for (int nt = 0; nt < 4; nt++) Bf[nt] = gB2frag[(kc * 4 + nt) * 32 + l];

        const int e0 = kc * 16 + 2 * t;
        const int o0 = (e0 / 9) * 264 + (e0 % 9);
        const int o1 = ((e0 + 1) / 9) * 264 + ((e0 + 1) % 9);
        const int o8 = ((e0 + 8) / 9) * 264 + ((e0 + 8) % 9);
        const int o9 = ((e0 + 9) / 9) * 264 + ((e0 + 9) % 9);

#pragma unroll
        for (int mt = 0; mt < 2; mt++) {
            const int ra = r0c + mt * 32;      // row, x2
            const int rb = ra + 16;            // row+8, x2
            float fA0 = smem_pool[o0 + ra], fA1 = smem_pool[o1 + ra];
            float fB0 = smem_pool[o0 + rb], fB1 = smem_pool[o1 + rb];
            float fC0 = smem_pool[o8 + ra], fC1 = smem_pool[o9 + ra];
            float fD0 = smem_pool[o8 + rb], fD1 = smem_pool[o9 + rb];
            uint32_t a0 = cvt2bf(fA0, fA1), a1 = cvt2bf(fB0, fB1);
            uint32_t a2 = cvt2bf(fC0, fC1), a3 = cvt2bf(fD0, fD1);
            uint32_t a0l = cvt2bf(fA0 - bf_lo(a0), fA1 - bf_hi(a0));
            uint32_t a1l = cvt2bf(fB0 - bf_lo(a1), fB1 - bf_hi(a1));
            uint32_t a2l = cvt2bf(fC0 - bf_lo(a2), fC1 - bf_hi(a2));
            uint32_t a3l = cvt2bf(fD0 - bf_lo(a3), fD1 - bf_hi(a3));
#pragma unroll
            for (int nt = 0; nt < 4; nt++)
                mma16816(D[mt][nt], a0, a1, a2, a3, Bf[nt].x, Bf[nt].y);
#pragma unroll
            for (int nt = 0; nt < 4; nt++)
                mma16816(D[mt][nt], a0l, a1l, a2l, a3l, Bf[nt].x, Bf[nt].y);
        }
    }
    __syncthreads();   // xs dead; reuse smem_pool as D buffer [128][32]

#pragma unroll
    for (int mt = 0; mt < 2; mt++) {
        int r = w * 32 + mt * 16 + g;
#pragma unroll
        for (int nt = 0; nt < 4; nt++) {
            int c = nt * 8 + 2 * t;
            smem_pool[r * 32 + c]       = D[mt][nt][0];
            smem_pool[r * 32 + c + 1]   = D[mt][nt][1];
            smem_pool[(r + 8) * 32 + c]     = D[mt][nt][2];
            smem_pool[(r + 8) * 32 + c + 1] = D[mt][nt][3];
        }
    }
    __syncthreads();

    // BN + ht + maxpool2 + store [b][pooled][32]
#pragma unroll
    for (int j = 0; j < 16; j++) {
        int idx = j * 128 + tid;
        int pr = idx >> 5, c = idx & 31;
        float s = psc2f[c], sh = pshf2[c];
        float y0 = ht(fmaf(smem_pool[(2 * pr) * 32 + c], s, sh));
        float y1 = ht(fmaf(smem_pool[(2 * pr + 1) * 32 + c], s, sh));
        g_buf2f[(b * 1024 + tile * 64 + pr) * 32 + c] = fmaxf(y0, y1);
    }
}

// ---------------------------------------------------------------------------
// Kernel 3: conv3 (32->64) via mma.sync bf16 (2-way split) + BN + ht + pool
//           + pooled store for mean. Block: 128 pos x 64 ch, K = 160.
// grid (4, 256), 128 thr. xs[col][ci] fp32 (col = 2*row + k), stride 33.
// ---------------------------------------------------------------------------
__global__ __launch_bounds__(128) void k3()
{
    __shared__ float smem_pool[259 * 33];   // 34.2 KB; reused as D (128*64)

    const int tile = blockIdx.x;   // 0..3
    const int b = blockIdx.y;
    const int tid = threadIdx.x;
    const int w = tid >> 5, l = tid & 31;
    const int g = l >> 2, t = l & 3;

    const int rbase = tile * 256 - 2;
    for (int i = tid; i < 259 * 32; i += 128) {
        int row = i >> 5, c = i & 31;
        int gi = rbase + row;
        smem_pool[row * 33 + c] = (gi >= 0 && gi < 1024)
                                ? g_buf2f[(b * 1024 + gi) * 32 + c] : 0.f;
    }
    __syncthreads();

    float D[2][8][4];
#pragma unroll
    for (int mt = 0; mt < 2; mt++)
#pragma unroll
        for (int nt = 0; nt < 8; nt++)
#pragma unroll
            for (int j = 0; j < 4; j++) D[mt][nt][j] = 0.f;

    const int r0c = 66 * (w * 32 + g);   // row term: (2*row)*33

#pragma unroll 1
    for (int kc = 0; kc < 10; kc++) {
        uint2 Bf[8];
#pragma unroll
        for (int nt = 0; nt < 8; nt++) Bf[nt] = gB3frag[(kc * 8 + nt) * 32 + l];

        const int e0 = kc * 16 + 2 * t;
        const int o0 = 33 * (e0 % 5) + (e0 / 5);
        const int o1 = 33 * ((e0 + 1) % 5) + ((e0 + 1) / 5);
        const int o8 = 33 * ((e0 + 8) % 5) + ((e0 + 8) / 5);
        const int o9 = 33 * ((e0 + 9) % 5) + ((e0 + 9) / 5);

#pragma unroll
        for (int mt = 0; mt < 2; mt++) {
            const int ra = r0c + mt * 16 * 66;
            const int rb = ra + 8 * 66;
            float fA0 = smem_pool[o0 + ra], fA1 = smem_pool[o1 + ra];
            float fB0 = smem_pool[o0 + rb], fB1 = smem_pool[o1 + rb];
            float fC0 = smem_pool[o8 + ra], fC1 = smem_pool[o9 + ra];
            float fD0 = smem_pool[o8 + rb], fD1 = smem_pool[o9 + rb];
            uint32_t a0 = cvt2bf(fA0, fA1), a1 = cvt2bf(fB0, fB1);
            uint32_t a2 = cvt2bf(fC0, fC1), a3 = cvt2bf(fD0, fD1);
            uint32_t a0l = cvt2bf(fA0 - bf_lo(a0), fA1 - bf_hi(a0));
            uint32_t a1l = cvt2bf(fB0 - bf_lo(a1), fB1 - bf_hi(a1));
            uint32_t a2l = cvt2bf(fC0 - bf_lo(a2), fC1 - bf_hi(a2));
            uint32_t a3l = cvt2bf(fD0 - bf_lo(a3), fD1 - bf_hi(a3));
#pragma unroll
            for (int nt = 0; nt < 8; nt++)
                mma16816(D[mt][nt], a0, a1, a2, a3, Bf[nt].x, Bf[nt].y);
#pragma unroll
            for (int nt = 0; nt < 8; nt++)
                mma16816(D[mt][nt], a0l, a1l, a2l, a3l, Bf[nt].x, Bf[nt].y);
        }
    }
    __syncthreads();   // xs dead; reuse as D buffer [128][64]

#pragma unroll
    for (int mt = 0; mt < 2; mt++) {
        int r = w * 32 + mt * 16 + g;
#pragma unroll
        for (int nt = 0; nt < 8; nt++) {
            int c = nt * 8 + 2 * t;
            smem_pool[r * 64 + c]       = D[mt][nt][0];
            smem_pool[r * 64 + c + 1]   = D[mt][nt][1];
            smem_pool[(r + 8) * 64 + c]     = D[mt][nt][2];
            smem_pool[(r + 8) * 64 + c + 1] = D[mt][nt][3];
        }
    }
    __syncthreads();

#pragma unroll
    for (int j = 0; j < 32; j++) {
        int idx = j * 128 + tid;
        int pr = idx >> 6, c = idx & 63;
        float s = psc3f[c], sh = pshf3[c];
        float y0 = ht(fmaf(smem_pool[(2 * pr) * 64 + c], s, sh));
        float y1 = ht(fmaf(smem_pool[(2 * pr + 1) * 64 + c], s, sh));
        g_buf3f[(b * 256 + tile * 64 + pr) * 64 + c] = fmaxf(y0, y1);
    }
}

// ---------------------------------------------------------------------------
// Kernel 4: mean over 256 pooled pos, concat rms, fc1 + ht, fc2.
// ---------------------------------------------------------------------------
__global__ __launch_bounds__(64) void k4(
    const float* __restrict__ rms,
    const float* __restrict__ fc1w, const float* __restrict__ fc1b,
    const float* __restrict__ fc2w, const float* __restrict__ fc2b,
    float* __restrict__ out)
{
    __shared__ float comb[65];
    __shared__ float h1[32];
    const int b = blockIdx.x;
    const int tid = threadIdx.x;

    {
        float s = 0.f;
        const float* basep = g_buf3f + b * 256 * 64 + tid;
#pragma unroll 8
        for (int P = 0; P < 256; P++) s += basep[P * 64];
        comb[tid] = s * (1.f / 256.f);
    }
    if (tid == 0) comb[64] = rms[b];
    __syncthreads();

    if (tid < 32) {
        float a = fc1b[tid];
        const float* wr = fc1w + tid * 65;
#pragma unroll
        for (int i = 0; i < 65; i++) a = fmaf(comb[i], wr[i], a);
        h1[tid] = ht(a);
    }
    __syncthreads();

    if (tid < 2) {
        float a = fc2b[tid];
        const float* wr = fc2w + tid * 32;
#pragma unroll
        for (int i = 0; i < 32; i++) a = fmaf(h1[i], wr[i], a);
        out[b * 2 + tid] = a;
    }
}

// ---------------------------------------------------------------------------
extern "C" void kernel_launch(void* const* d_in, const int* in_sizes, int n_in,
                              void* d_out, int out_size)
{
    const float* x     = (const float*)d_in[0];
    const float* rms   = (const float*)d_in[1];
    const float* w1    = (const float*)d_in[2];
    const float* g1    = (const float*)d_in[3];
    const float* b1    = (const float*)d_in[4];
    const float* m1    = (const float*)d_in[5];
    const float* v1    = (const float*)d_in[6];
    const float* w2    = (const float*)d_in[7];
    const float* g2    = (const float*)d_in[8];
    const float* b2    = (const float*)d_in[9];
    const float* m2    = (const float*)d_in[10];
    const float* v2    = (const float*)d_in[11];
    const float* w3    = (const float*)d_in[12];
    const float* g3    = (const float*)d_in[13];
    const float* b3    = (const float*)d_in[14];
    const float* m3    = (const float*)d_in[15];
    const float* v3    = (const float*)d_in[16];
    const float* fc1w  = (const float*)d_in[17];
    const float* fc1b  = (const float*)d_in[18];
    const float* fc2w  = (const float*)d_in[19];
    const float* fc2b  = (const float*)d_in[20];
    float* out = (float*)d_out;

    k0a<<<1, 256>>>(w1, g1, b1, m1, v1, w2, g2, b2, m2, v2);
    k0b<<<1, 256>>>(w3, g3, b3, m3, v3);
    k1<<<dim3(16, 128), 128>>>(x);
    k2<<<dim3(16, 256), 128>>>();
    k3<<<dim3(4, 256), 128>>>();
    k4<<<256, 64>>>(rms, fc1w, fc1b, fc2w, fc2b, out);
}